// round 11
// baseline (speedup 1.0000x reference)
#include <cuda_runtime.h>
#include <cuda_bf16.h>
#include <math.h>
#include <cstdint>

static constexpr int NMAX = 50000;
static constexpr int EMAX = 800000;
static constexpr int SWW = 144;  // B row stride in words (128 data + 16 pad; 144%32==16)

// ---------------- scratch (device globals; no allocation allowed) ----------
__device__ __align__(16) float g_bc[128];                 // bemb @ W1
__device__ __align__(16) float g_h1[(size_t)NMAX * 128];  // layer1 pre-attn features
__device__ __align__(16) float g_y1[(size_t)NMAX * 128];  // elu(aggr1 + b1)
__device__ __align__(16) float g_h2[(size_t)NMAX * 64];   // layer2 pre-attn features
__device__ __align__(16) float g_as1[NMAX * 4];
__device__ __align__(16) float g_ad1[NMAX * 4];
__device__ __align__(16) float g_as2[NMAX * 4];
__device__ __align__(16) float g_ad2[NMAX * 4];
__device__ int g_deg[NMAX];
__device__ int g_cur[NMAX];
__device__ int g_off[NMAX + 1];
__device__ int g_csrc[EMAX];
__device__ unsigned g_lb[64];  // lookback state: flag(2b)<<30 | value
// B tiles, fragment-interleaved: per row (n), per ks (16 words):
//   word[ks*16 + cA*4 + {0,1,2,3}] = {hi(8ks+cA), hi(8ks+cA+4), lo(...), lo(...)}
__device__ __align__(16) uint32_t g_B1w[128 * SWW];  // Wc  (N=128,K=128)
__device__ __align__(16) uint32_t g_B2w[64 * SWW];   // W2  (N=64, K=128)

// ---------------- helpers ---------------------------------------------------
__device__ __forceinline__ void mma16816(float* d, const uint32_t* a, uint32_t b0,
                                         uint32_t b1) {
    asm volatile(
        "mma.sync.aligned.m16n8k16.row.col.f32.bf16.bf16.f32 "
        "{%0,%1,%2,%3}, {%4,%5,%6,%7}, {%8,%9}, {%0,%1,%2,%3};"
        : "+f"(d[0]), "+f"(d[1]), "+f"(d[2]), "+f"(d[3])
        : "r"(a[0]), "r"(a[1]), "r"(a[2]), "r"(a[3]), "r"(b0), "r"(b1));
}
__device__ __forceinline__ uint32_t pack_bf2(__nv_bfloat16 a, __nv_bfloat16 b) {
    return (uint32_t)*(unsigned short*)&a | ((uint32_t)*(unsigned short*)&b << 16);
}
__device__ __forceinline__ void cvt2(float2 f, uint32_t& h, uint32_t& l) {
    __nv_bfloat16 b0 = __float2bfloat16(f.x);
    __nv_bfloat16 b1 = __float2bfloat16(f.y);
    h = pack_bf2(b0, b1);
    l = pack_bf2(__float2bfloat16(f.x - __bfloat162float(b0)),
                 __float2bfloat16(f.y - __bfloat162float(b1)));
}
__device__ __forceinline__ float leaky02(float x) { return x > 0.f ? x : 0.2f * x; }
// short offset (within a row, in shorts) for element k of hi (slotbase 0) / lo (+2)
__device__ __forceinline__ int bslot(int k) {
    int p = k >> 1, ks = p >> 3, r = p & 7;
    int cAx = r & 3, slot = r >> 2;
    return (ks * 16 + cAx * 4 + slot) * 2 + (k & 1);
}

// ---------------- prep: weights -> interleaved bf16 B tiles; bc; init ------
__global__ void k_prep(const float* __restrict__ Wemb, const float* __restrict__ bemb,
                       const float* __restrict__ W1, const float* __restrict__ W2,
                       int n) {
    int t = blockIdx.x * blockDim.x + threadIdx.x;
    if (t < 128 * 128) {
        int c = t & 127, k = t >> 7;
        float s = 0.f;
#pragma unroll
        for (int m = 0; m < 32; m++) s = fmaf(Wemb[k * 32 + m], W1[m * 128 + c], s);
        __nv_bfloat16 h = __float2bfloat16(s);
        __nv_bfloat16 l = __float2bfloat16(s - __bfloat162float(h));
        unsigned short* B = (unsigned short*)g_B1w;
        int so = bslot(k);
        B[c * SWW * 2 + so] = *(unsigned short*)&h;
        B[c * SWW * 2 + so + 4] = *(unsigned short*)&l;
    } else if (t < 128 * 128 + 64 * 128) {
        int u = t - 128 * 128;
        int c = u & 63, k = u >> 6;
        float s = W2[k * 64 + c];
        __nv_bfloat16 h = __float2bfloat16(s);
        __nv_bfloat16 l = __float2bfloat16(s - __bfloat162float(h));
        unsigned short* B = (unsigned short*)g_B2w;
        int so = bslot(k);
        B[c * SWW * 2 + so] = *(unsigned short*)&h;
        B[c * SWW * 2 + so + 4] = *(unsigned short*)&l;
    } else if (t < 128 * 128 + 64 * 128 + 128) {
        int c = t - (128 * 128 + 64 * 128);
        float s = 0.f;
#pragma unroll
        for (int m = 0; m < 32; m++) s = fmaf(bemb[m], W1[m * 128 + c], s);
        g_bc[c] = s;
    } else if (t < 128 * 128 + 64 * 128 + 128 + 64) {
        g_lb[t - (128 * 128 + 64 * 128 + 128)] = 0u;
    } else {
        int i = t - (128 * 128 + 64 * 128 + 128 + 64);
        if (i < n) g_deg[i] = 0;
    }
}

// ---------------- CSR build ------------------------------------------------
__global__ void k_hist(const int* __restrict__ dst, int e) {
    int i = blockIdx.x * blockDim.x + threadIdx.x;
    if (i < e) atomicAdd(&g_deg[dst[i]], 1);
}

// single-pass decoupled-lookback exclusive scan: g_deg -> g_off, g_cur
__global__ void __launch_bounds__(1024) k_scan(int n) {
    __shared__ int ws[32];
    __shared__ int sprefix;
    int b = blockIdx.x, t = threadIdx.x;
    int lane = t & 31, w = t >> 5;
    int i = b * 1024 + t;
    int v = (i < n) ? g_deg[i] : 0;
    int x = v;
#pragma unroll
    for (int o = 1; o < 32; o <<= 1) {
        int y = __shfl_up_sync(0xffffffffu, x, o);
        if (lane >= o) x += y;
    }
    if (lane == 31) ws[w] = x;
    __syncthreads();
    if (w == 0) {
        int s = ws[lane];
#pragma unroll
        for (int o = 1; o < 32; o <<= 1) {
            int y = __shfl_up_sync(0xffffffffu, s, o);
            if (lane >= o) s += y;
        }
        ws[lane] = s;
    }
    __syncthreads();
    if (t == 0) {
        unsigned total = (unsigned)ws[31];
        if (b == 0) {
            atomicExch(&g_lb[0], (2u << 30) | total);
            sprefix = 0;
        } else {
            atomicExch(&g_lb[b], (1u << 30) | total);
            unsigned pref = 0;
            int p = b - 1;
            while (true) {
                unsigned u = atomicOr(&g_lb[p], 0u);
                unsigned f = u >> 30;
                if (f == 0u) continue;
                pref += u & 0x3FFFFFFFu;
                if (f == 2u) break;
                p--;
            }
            atomicExch(&g_lb[b], (2u << 30) | (pref + total));
            sprefix = (int)pref;
        }
    }
    __syncthreads();
    int incl = sprefix + (w ? ws[w - 1] : 0) + x;
    if (i < n) {
        g_off[i + 1] = incl;
        g_cur[i] = incl - v;
    }
    if (i == 0) g_off[0] = 0;
}

__global__ void k_scatter(const int* __restrict__ src, const int* __restrict__ dst, int e) {
    int i = blockIdx.x * blockDim.x + threadIdx.x;
    if (i < e) {
        int p = atomicAdd(&g_cur[dst[i]], 1);
        g_csrc[p] = src[i];
    }
}

// ---------------- HMMA GEMM + attention epilogue ---------------------------
// C[128 x NOUT] per CTA, rows offset by rbase; split-bf16 (hh + hl + lh).
template <int NOUT, bool L1>
__global__ void __launch_bounds__(256) k_gemm_mma(
    const float* __restrict__ Xin, const float* __restrict__ a_src,
    const float* __restrict__ a_dst, int n, int rbase) {
    constexpr int NT = NOUT / 8;
    constexpr int CSH = (NOUT == 128) ? 5 : 4;
    constexpr int BT = NOUT * SWW;  // words
    extern __shared__ uint32_t smw[];
    uint32_t* sB = smw;

    int tid = threadIdx.x, w = tid >> 5, lane = tid & 31;
    int bid = blockIdx.x;
    const float* X = L1 ? Xin : (const float*)g_y1;
    const uint32_t* Bg = L1 ? g_B1w : g_B2w;
    float* Hout = L1 ? g_h1 : g_h2;
    float* as_out = L1 ? g_as1 : g_as2;
    float* ad_out = L1 ? g_ad1 : g_ad2;

    for (int i = tid; i < BT / 4; i += 256)
        ((float4*)sB)[i] = ((const float4*)Bg)[i];
    __syncthreads();

    int r0g = rbase + bid * 128 + 16 * w + (lane >> 2);
    const float* pX0 = X + (size_t)min(r0g, n - 1) * 128;
    const float* pX1 = X + (size_t)min(r0g + 8, n - 1) * 128;
    int cA = lane & 3;
    int brow = (lane >> 2) * SWW + cA * 4;

    float acc[NT][4];
#pragma unroll
    for (int t = 0; t < NT; t++)
#pragma unroll
        for (int j = 0; j < 4; j++) acc[t][j] = 0.f;

    // prefetch ks=0
    int c0 = 2 * cA;
    float2 f0a = *(const float2*)(pX0 + c0);
    float2 f0b = *(const float2*)(pX0 + c0 + 8);
    float2 f1a = *(const float2*)(pX1 + c0);
    float2 f1b = *(const float2*)(pX1 + c0 + 8);

#pragma unroll
    for (int ks = 0; ks < 8; ks++) {
        float2 c0a = f0a, c0b = f0b, c1a = f1a, c1b = f1b;
        if (ks < 7) {
            int cn = 2 * (8 * (ks + 1) + cA);
            f0a = *(const float2*)(pX0 + cn);
            f0b = *(const float2*)(pX0 + cn + 8);
            f1a = *(const float2*)(pX1 + cn);
            f1b = *(const float2*)(pX1 + cn + 8);
        }
        uint32_t ah[4], al[4];
        cvt2(c0a, ah[0], al[0]);
        cvt2(c1a, ah[1], al[1]);
        cvt2(c0b, ah[2], al[2]);
        cvt2(c1b, ah[3], al[3]);
        int kb = ks * 16 + brow;
#pragma unroll
        for (int nt = 0; nt < NT; nt++) {
            uint4 bv = *(const uint4*)&sB[nt * 8 * SWW + kb];
            mma16816(acc[nt], ah, bv.x, bv.y);
            mma16816(acc[nt], ah, bv.z, bv.w);
            mma16816(acc[nt], al, bv.x, bv.y);
        }
    }

    int row0 = r0g;
    int row1 = r0g + 8;
    float asv0[4] = {0, 0, 0, 0}, adv0[4] = {0, 0, 0, 0};
    float asv1[4] = {0, 0, 0, 0}, adv1[4] = {0, 0, 0, 0};
#pragma unroll
    for (int nt = 0; nt < NT; nt++) {
        int c = nt * 8 + (lane & 3) * 2;
        float b0 = L1 ? g_bc[c] : 0.f, b1 = L1 ? g_bc[c + 1] : 0.f;
        float v0 = acc[nt][0] + b0, v1 = acc[nt][1] + b1;
        float v2 = acc[nt][2] + b0, v3 = acc[nt][3] + b1;
        int h = c >> CSH;
        float s0 = __ldg(a_src + c), s1 = __ldg(a_src + c + 1);
        float d0 = __ldg(a_dst + c), d1 = __ldg(a_dst + c + 1);
        asv0[h] = fmaf(v0, s0, fmaf(v1, s1, asv0[h]));
        adv0[h] = fmaf(v0, d0, fmaf(v1, d1, adv0[h]));
        asv1[h] = fmaf(v2, s0, fmaf(v3, s1, asv1[h]));
        adv1[h] = fmaf(v2, d0, fmaf(v3, d1, adv1[h]));
        if (row0 < n) *(float2*)&Hout[(size_t)row0 * NOUT + c] = make_float2(v0, v1);
        if (row1 < n) *(float2*)&Hout[(size_t)row1 * NOUT + c] = make_float2(v2, v3);
    }
#pragma unroll
    for (int o = 1; o <= 2; o <<= 1) {
#pragma unroll
        for (int h = 0; h < 4; h++) {
            asv0[h] += __shfl_xor_sync(0xffffffffu, asv0[h], o);
            adv0[h] += __shfl_xor_sync(0xffffffffu, adv0[h], o);
            asv1[h] += __shfl_xor_sync(0xffffffffu, asv1[h], o);
            adv1[h] += __shfl_xor_sync(0xffffffffu, adv1[h], o);
        }
    }
    if ((lane & 3) == 0) {
        if (row0 < n) {
            *(float4*)&as_out[row0 * 4] = make_float4(asv0[0], asv0[1], asv0[2], asv0[3]);
            *(float4*)&ad_out[row0 * 4] = make_float4(adv0[0], adv0[1], adv0[2], adv0[3]);
        }
        if (row1 < n) {
            *(float4*)&as_out[row1 * 4] = make_float4(asv1[0], asv1[1], asv1[2], asv1[3]);
            *(float4*)&ad_out[row1 * 4] = make_float4(adv1[0], adv1[1], adv1[2], adv1[3]);
        }
    }
}

// ---------------- layer-1 aggregation over node range [lo,hi) --------------
__global__ void __launch_bounds__(256) k_aggr1(const float* __restrict__ b1,
                                               int lo, int hi) {
    int warp = threadIdx.x >> 5, lane = threadIdx.x & 31;
    int node = lo + blockIdx.x * 8 + warp;
    if (node >= hi) return;
    int beg = g_off[node], end = g_off[node + 1];
    int h = lane >> 3, col = 4 * lane;
    float adv = g_ad1[node * 4 + h];
    float s = 0.f;
    float ax = 0.f, ay = 0.f, az = 0.f, aw = 0.f;

    for (int idx = beg; idx < end; idx += 4) {
        bool n1 = idx + 1 < end, n2 = idx + 2 < end, n3 = idx + 3 < end;
        int s0 = __ldg(&g_csrc[idx]);
        int s1 = n1 ? __ldg(&g_csrc[idx + 1]) : s0;
        int s2 = n2 ? __ldg(&g_csrc[idx + 2]) : s0;
        int s3 = n3 ? __ldg(&g_csrc[idx + 3]) : s0;
        float a0 = __ldg(&g_as1[s0 * 4 + h]);
        float a1 = __ldg(&g_as1[s1 * 4 + h]);
        float a2 = __ldg(&g_as1[s2 * 4 + h]);
        float a3 = __ldg(&g_as1[s3 * 4 + h]);
        float4 v0 = *(const float4*)&g_h1[(size_t)s0 * 128 + col];
        float4 v1 = *(const float4*)&g_h1[(size_t)s1 * 128 + col];
        float4 v2 = *(const float4*)&g_h1[(size_t)s2 * 128 + col];
        float4 v3 = *(const float4*)&g_h1[(size_t)s3 * 128 + col];
        float e0 = __expf(leaky02(a0 + adv));
        float e1 = n1 ? __expf(leaky02(a1 + adv)) : 0.f;
        float e2 = n2 ? __expf(leaky02(a2 + adv)) : 0.f;
        float e3 = n3 ? __expf(leaky02(a3 + adv)) : 0.f;
        s += (e0 + e1) + (e2 + e3);
        ax = fmaf(e0, v0.x, ax); ay = fmaf(e0, v0.y, ay);
        az = fmaf(e0, v0.z, az); aw = fmaf(e0, v0.w, aw);
        ax = fmaf(e1, v1.x, ax); ay = fmaf(e1, v1.y, ay);
        az = fmaf(e1, v1.z, az); aw = fmaf(e1, v1.w, aw);
        ax = fmaf(e2, v2.x, ax); ay = fmaf(e2, v2.y, ay);
        az = fmaf(e2, v2.z, az); aw = fmaf(e2, v2.w, aw);
        ax = fmaf(e3, v3.x, ax); ay = fmaf(e3, v3.y, ay);
        az = fmaf(e3, v3.z, az); aw = fmaf(e3, v3.w, aw);
    }
    float inv = 1.f / (s + 1e-16f);
    float4 bb = *(const float4*)&b1[col];
    float o0 = ax * inv + bb.x;
    float o1 = ay * inv + bb.y;
    float o2 = az * inv + bb.z;
    float o3 = aw * inv + bb.w;
    o0 = o0 > 0.f ? o0 : expm1f(o0);
    o1 = o1 > 0.f ? o1 : expm1f(o1);
    o2 = o2 > 0.f ? o2 : expm1f(o2);
    o3 = o3 > 0.f ? o3 : expm1f(o3);
    *(float4*)&g_y1[(size_t)node * 128 + col] = make_float4(o0, o1, o2, o3);
}

// ---------------- layer-2 aggregation + head-mean + log_softmax ------------
__global__ void __launch_bounds__(256) k_aggr2(const float* __restrict__ b2,
                                               float* __restrict__ out, int n) {
    int warp = threadIdx.x >> 5, lane = threadIdx.x & 31;
    int node = blockIdx.x * 8 + warp;
    if (node >= n) return;
    int beg = g_off[node], end = g_off[node + 1];
    int h = lane >> 3, col = 2 * lane;
    float adv = g_ad2[node * 4 + h];
    float s = 0.f, ax = 0.f, ay = 0.f;

    for (int idx = beg; idx < end; idx += 4) {
        bool n1 = idx + 1 < end, n2 = idx + 2 < end, n3 = idx + 3 < end;
        int s0 = __ldg(&g_csrc[idx]);
        int s1 = n1 ? __ldg(&g_csrc[idx + 1]) : s0;
        int s2 = n2 ? __ldg(&g_csrc[idx + 2]) : s0;
        int s3 = n3 ? __ldg(&g_csrc[idx + 3]) : s0;
        float a0 = __ldg(&g_as2[s0 * 4 + h]);
        float a1 = __ldg(&g_as2[s1 * 4 + h]);
        float a2 = __ldg(&g_as2[s2 * 4 + h]);
        float a3 = __ldg(&g_as2[s3 * 4 + h]);
        float2 v0 = *(const float2*)&g_h2[(size_t)s0 * 64 + col];
        float2 v1 = *(const float2*)&g_h2[(size_t)s1 * 64 + col];
        float2 v2 = *(const float2*)&g_h2[(size_t)s2 * 64 + col];
        float2 v3 = *(const float2*)&g_h2[(size_t)s3 * 64 + col];
        float e0 = __expf(leaky02(a0 + adv));
        float e1 = n1 ? __expf(leaky02(a1 + adv)) : 0.f;
        float e2 = n2 ? __expf(leaky02(a2 + adv)) : 0.f;
        float e3 = n3 ? __expf(leaky02(a3 + adv)) : 0.f;
        s += (e0 + e1) + (e2 + e3);
        ax = fmaf(e0, v0.x, ax); ay = fmaf(e0, v0.y, ay);
        ax = fmaf(e1, v1.x, ax); ay = fmaf(e1, v1.y, ay);
        ax = fmaf(e2, v2.x, ax); ay = fmaf(e2, v2.y, ay);
        ax = fmaf(e3, v3.x, ax); ay = fmaf(e3, v3.y, ay);
    }
    float inv = 1.f / (s + 1e-16f);
    float ox = ax * inv, oy = ay * inv;
    ox += __shfl_xor_sync(0xffffffffu, ox, 8);
    oy += __shfl_xor_sync(0xffffffffu, oy, 8);
    ox += __shfl_xor_sync(0xffffffffu, ox, 16);
    oy += __shfl_xor_sync(0xffffffffu, oy, 16);
    int c0 = 2 * (lane & 7);
    ox = ox * 0.25f + b2[c0];
    oy = oy * 0.25f + b2[c0 + 1];
    float mx = fmaxf(ox, oy);
#pragma unroll
    for (int o = 4; o; o >>= 1) mx = fmaxf(mx, __shfl_xor_sync(0xffffffffu, mx, o));
    float se = __expf(ox - mx) + __expf(oy - mx);
#pragma unroll
    for (int o = 4; o; o >>= 1) se += __shfl_xor_sync(0xffffffffu, se, o);
    float lse = mx + logf(se);
    if (lane < 8)
        *(float2*)&out[(size_t)node * 16 + c0] = make_float2(ox - lse, oy - lse);
}

// ---------------- launcher: fork CSR || GEMM1; pipeline aggr1/gemm2 --------
extern "C" void kernel_launch(void* const* d_in, const int* in_sizes, int n_in,
                              void* d_out, int out_size) {
    const float* x = (const float*)d_in[0];
    const int* ei = (const int*)d_in[1];
    const float* Wemb = (const float*)d_in[2];
    const float* bemb = (const float*)d_in[3];
    const float* W1 = (const float*)d_in[4];
    const float* a_src1 = (const float*)d_in[5];
    const float* a_dst1 = (const float*)d_in[6];
    const float* b1 = (const float*)d_in[7];
    const float* W2 = (const float*)d_in[8];
    const float* a_src2 = (const float*)d_in[9];
    const float* a_dst2 = (const float*)d_in[10];
    const float* b2 = (const float*)d_in[11];
    float* out = (float*)d_out;

    int n = in_sizes[0] / 128;
    int e = in_sizes[1] / 2;
    if (n <= 0 || n > NMAX || e <= 0 || e > EMAX) return;
    const int* src = ei;
    const int* dst = ei + e;
    int nb = (n + 1023) / 1024;
    int nbg = (n + 127) / 128;

    // one-time side-stream + events (created on the first, non-captured call)
    static cudaStream_t sB = nullptr;
    static cudaEvent_t evF = nullptr, evJ = nullptr, evG = nullptr;
    static cudaEvent_t evA[4] = {nullptr, nullptr, nullptr, nullptr};
    if (sB == nullptr) {
        cudaStreamCreateWithFlags(&sB, cudaStreamNonBlocking);
        cudaEventCreateWithFlags(&evF, cudaEventDisableTiming);
        cudaEventCreateWithFlags(&evJ, cudaEventDisableTiming);
        cudaEventCreateWithFlags(&evG, cudaEventDisableTiming);
        for (int c = 0; c < 4; c++) cudaEventCreateWithFlags(&evA[c], cudaEventDisableTiming);
    }

    int smem1 = 128 * SWW * 4;  // 73728
    int smem2 = 64 * SWW * 4;   // 36864
    cudaFuncSetAttribute(k_gemm_mma<128, true>,
                         cudaFuncAttributeMaxDynamicSharedMemorySize, smem1);
    cudaFuncSetAttribute(k_gemm_mma<64, false>,
                         cudaFuncAttributeMaxDynamicSharedMemorySize, smem2);

    int prep_items = 128 * 128 + 64 * 128 + 128 + 64 + n;

    // main stream: prep, then fork
    k_prep<<<(prep_items + 255) / 256, 256>>>(Wemb, bemb, W1, W2, n);
    cudaEventRecord(evF, 0);

    // branch B (side stream): CSR build
    cudaStreamWaitEvent(sB, evF, 0);
    k_hist<<<(e + 255) / 256, 256, 0, sB>>>(dst, e);
    k_scan<<<nb, 1024, 0, sB>>>(n);
    k_scatter<<<(e + 255) / 256, 256, 0, sB>>>(src, dst, e);
    cudaEventRecord(evJ, sB);

    // branch A (main stream): GEMM1 overlaps the CSR build
    k_gemm_mma<128, true><<<nbg, 256, smem1>>>(x, a_src1, a_dst1, n, 0);

    // join: aggr1 needs CSR + gemm1
    cudaStreamWaitEvent(0, evJ, 0);

    // pipelined tail: aggr1 chunks on stream 0, gemm2 chunks on sB
    int tiles_per = (nbg + 3) / 4;
    for (int c = 0; c < 4; c++) {
        int tlo = c * tiles_per;
        if (tlo >= nbg) break;
        int tcnt = min(tiles_per, nbg - tlo);
        int lo = tlo * 128;
        int hi = min(lo + tcnt * 128, n);
        k_aggr1<<<(hi - lo + 7) / 8, 256>>>(b1, lo, hi);
        cudaEventRecord(evA[c], 0);
        cudaStreamWaitEvent(sB, evA[c], 0);
        k_gemm_mma<64, false><<<tcnt, 256, smem2, sB>>>(nullptr, a_src2, a_dst2, n, lo);
    }
    cudaEventRecord(evG, sB);

    // aggr2 needs all gemm2 chunks
    cudaStreamWaitEvent(0, evG, 0);
    k_aggr2<<<(n + 7) / 8, 256>>>(b2, out, n);
}

// round 13
// speedup vs baseline: 1.0196x; 1.0196x over previous
#include <cuda_runtime.h>
#include <cuda_bf16.h>
#include <math.h>
#include <cstdint>

static constexpr int NMAX = 50000;
static constexpr int EMAX = 800000;
static constexpr int SWW = 144;  // B row stride in words (128 data + 16 pad; 144%32==16)

// ---------------- scratch (device globals; no allocation allowed) ----------
__device__ __align__(16) float g_bc[128];                 // bemb @ W1
__device__ __align__(16) float g_h1[(size_t)NMAX * 128];  // layer1 pre-attn features
__device__ __align__(16) float g_y1[(size_t)NMAX * 128];  // elu(aggr1 + b1)
__device__ __align__(16) float g_h2[(size_t)NMAX * 64];   // layer2 pre-attn features
__device__ __align__(16) float g_as1[NMAX * 4];
__device__ __align__(16) float g_ad1[NMAX * 4];
__device__ __align__(16) float g_as2[NMAX * 4];
__device__ __align__(16) float g_ad2[NMAX * 4];
__device__ int g_deg[NMAX];
__device__ int g_cur[NMAX];
__device__ int g_off[NMAX + 1];
__device__ int g_csrc[EMAX];
__device__ unsigned g_lb[64];  // lookback state: flag(2b)<<30 | value
// B tiles, fragment-interleaved: per row (n), per ks (16 words):
//   word[ks*16 + cA*4 + {0,1,2,3}] = {hi(8ks+cA), hi(8ks+cA+4), lo(...), lo(...)}
__device__ __align__(16) uint32_t g_B1w[128 * SWW];  // Wc  (N=128,K=128)
__device__ __align__(16) uint32_t g_B2w[64 * SWW];   // W2  (N=64, K=128)

// ---------------- helpers ---------------------------------------------------
__device__ __forceinline__ void mma16816(float* d, const uint32_t* a, uint32_t b0,
                                         uint32_t b1) {
    asm volatile(
        "mma.sync.aligned.m16n8k16.row.col.f32.bf16.bf16.f32 "
        "{%0,%1,%2,%3}, {%4,%5,%6,%7}, {%8,%9}, {%0,%1,%2,%3};"
        : "+f"(d[0]), "+f"(d[1]), "+f"(d[2]), "+f"(d[3])
        : "r"(a[0]), "r"(a[1]), "r"(a[2]), "r"(a[3]), "r"(b0), "r"(b1));
}
__device__ __forceinline__ uint32_t pack_bf2(__nv_bfloat16 a, __nv_bfloat16 b) {
    return (uint32_t)*(unsigned short*)&a | ((uint32_t)*(unsigned short*)&b << 16);
}
__device__ __forceinline__ void cvt2(float2 f, uint32_t& h, uint32_t& l) {
    __nv_bfloat16 b0 = __float2bfloat16(f.x);
    __nv_bfloat16 b1 = __float2bfloat16(f.y);
    h = pack_bf2(b0, b1);
    l = pack_bf2(__float2bfloat16(f.x - __bfloat162float(b0)),
                 __float2bfloat16(f.y - __bfloat162float(b1)));
}
__device__ __forceinline__ float leaky02(float x) { return x > 0.f ? x : 0.2f * x; }
// short offset (within a row, in shorts) for element k of hi (slotbase 0) / lo (+2)
__device__ __forceinline__ int bslot(int k) {
    int p = k >> 1, ks = p >> 3, r = p & 7;
    int cAx = r & 3, slot = r >> 2;
    return (ks * 16 + cAx * 4 + slot) * 2 + (k & 1);
}

// ---------------- prepW: weights -> interleaved bf16 B tiles + bc ----------
__global__ void k_prepW(const float* __restrict__ Wemb, const float* __restrict__ bemb,
                        const float* __restrict__ W1, const float* __restrict__ W2) {
    int t = blockIdx.x * blockDim.x + threadIdx.x;
    if (t < 128 * 128) {
        int c = t & 127, k = t >> 7;
        float s = 0.f;
#pragma unroll
        for (int m = 0; m < 32; m++) s = fmaf(Wemb[k * 32 + m], W1[m * 128 + c], s);
        __nv_bfloat16 h = __float2bfloat16(s);
        __nv_bfloat16 l = __float2bfloat16(s - __bfloat162float(h));
        unsigned short* B = (unsigned short*)g_B1w;
        int so = bslot(k);
        B[c * SWW * 2 + so] = *(unsigned short*)&h;
        B[c * SWW * 2 + so + 4] = *(unsigned short*)&l;
    } else if (t < 128 * 128 + 64 * 128) {
        int u = t - 128 * 128;
        int c = u & 63, k = u >> 6;
        float s = W2[k * 64 + c];
        __nv_bfloat16 h = __float2bfloat16(s);
        __nv_bfloat16 l = __float2bfloat16(s - __bfloat162float(h));
        unsigned short* B = (unsigned short*)g_B2w;
        int so = bslot(k);
        B[c * SWW * 2 + so] = *(unsigned short*)&h;
        B[c * SWW * 2 + so + 4] = *(unsigned short*)&l;
    } else if (t < 128 * 128 + 64 * 128 + 128) {
        int c = t - (128 * 128 + 64 * 128);
        float s = 0.f;
#pragma unroll
        for (int m = 0; m < 32; m++) s = fmaf(bemb[m], W1[m * 128 + c], s);
        g_bc[c] = s;
    }
}

// ---------------- prepG: zero deg + lookback flags (CSR branch) ------------
__global__ void k_prepG(int n) {
    int t = blockIdx.x * blockDim.x + threadIdx.x;
    if (t < 64) g_lb[t] = 0u;
    int i = t - 64;
    if (i >= 0 && i < n) g_deg[i] = 0;
}

// ---------------- CSR build ------------------------------------------------
__global__ void k_hist(const int* __restrict__ dst, int e) {
    int i = blockIdx.x * blockDim.x + threadIdx.x;
    if (i < e) atomicAdd(&g_deg[dst[i]], 1);
}

// single-pass decoupled-lookback exclusive scan: g_deg -> g_off, g_cur
__global__ void __launch_bounds__(1024) k_scan(int n) {
    __shared__ int ws[32];
    __shared__ int sprefix;
    int b = blockIdx.x, t = threadIdx.x;
    int lane = t & 31, w = t >> 5;
    int i = b * 1024 + t;
    int v = (i < n) ? g_deg[i] : 0;
    int x = v;
#pragma unroll
    for (int o = 1; o < 32; o <<= 1) {
        int y = __shfl_up_sync(0xffffffffu, x, o);
        if (lane >= o) x += y;
    }
    if (lane == 31) ws[w] = x;
    __syncthreads();
    if (w == 0) {
        int s = ws[lane];
#pragma unroll
        for (int o = 1; o < 32; o <<= 1) {
            int y = __shfl_up_sync(0xffffffffu, s, o);
            if (lane >= o) s += y;
        }
        ws[lane] = s;
    }
    __syncthreads();
    if (t == 0) {
        unsigned total = (unsigned)ws[31];
        if (b == 0) {
            atomicExch(&g_lb[0], (2u << 30) | total);
            sprefix = 0;
        } else {
            atomicExch(&g_lb[b], (1u << 30) | total);
            unsigned pref = 0;
            int p = b - 1;
            while (true) {
                unsigned u = atomicOr(&g_lb[p], 0u);
                unsigned f = u >> 30;
                if (f == 0u) continue;
                pref += u & 0x3FFFFFFFu;
                if (f == 2u) break;
                p--;
            }
            atomicExch(&g_lb[b], (2u << 30) | (pref + total));
            sprefix = (int)pref;
        }
    }
    __syncthreads();
    int incl = sprefix + (w ? ws[w - 1] : 0) + x;
    if (i < n) {
        g_off[i + 1] = incl;
        g_cur[i] = incl - v;
    }
    if (i == 0) g_off[0] = 0;
}

__global__ void k_scatter(const int* __restrict__ src, const int* __restrict__ dst, int e) {
    int i = blockIdx.x * blockDim.x + threadIdx.x;
    if (i < e) {
        int p = atomicAdd(&g_cur[dst[i]], 1);
        g_csrc[p] = src[i];
    }
}

// ---------------- HMMA GEMM + attention epilogue ---------------------------
// C[128 x NOUT] per CTA; split-bf16 (hh + hl + lh). 8 warps x 16 rows. A
// converted in registers from global (L1-resident). B fragments via ONE
// LDS.128 per (ks, n-tile): interleaved layout, conflict-free (SWW%32==16).
template <int NOUT, bool L1>
__global__ void __launch_bounds__(256) k_gemm_mma(
    const float* __restrict__ Xin, const float* __restrict__ a_src,
    const float* __restrict__ a_dst, int n) {
    constexpr int NT = NOUT / 8;
    constexpr int CSH = (NOUT == 128) ? 5 : 4;
    constexpr int BT = NOUT * SWW;  // words
    extern __shared__ uint32_t smw[];
    uint32_t* sB = smw;

    int tid = threadIdx.x, w = tid >> 5, lane = tid & 31;
    int bid = blockIdx.x;
    const float* X = L1 ? Xin : (const float*)g_y1;
    const uint32_t* Bg = L1 ? g_B1w : g_B2w;
    float* Hout = L1 ? g_h1 : g_h2;
    float* as_out = L1 ? g_as1 : g_as2;
    float* ad_out = L1 ? g_ad1 : g_ad2;

    for (int i = tid; i < BT / 4; i += 256)
        ((float4*)sB)[i] = ((const float4*)Bg)[i];
    __syncthreads();

    int r0g = bid * 128 + 16 * w + (lane >> 2);
    const float* pX0 = X + (size_t)min(r0g, n - 1) * 128;
    const float* pX1 = X + (size_t)min(r0g + 8, n - 1) * 128;
    int cA = lane & 3;
    int brow = (lane >> 2) * SWW + cA * 4;

    float acc[NT][4];
#pragma unroll
    for (int t = 0; t < NT; t++)
#pragma unroll
        for (int j = 0; j < 4; j++) acc[t][j] = 0.f;

    // prefetch ks=0
    int c0 = 2 * cA;
    float2 f0a = *(const float2*)(pX0 + c0);
    float2 f0b = *(const float2*)(pX0 + c0 + 8);
    float2 f1a = *(const float2*)(pX1 + c0);
    float2 f1b = *(const float2*)(pX1 + c0 + 8);

#pragma unroll
    for (int ks = 0; ks < 8; ks++) {
        float2 c0a = f0a, c0b = f0b, c1a = f1a, c1b = f1b;
        if (ks < 7) {
            int cn = 2 * (8 * (ks + 1) + cA);
            f0a = *(const float2*)(pX0 + cn);
            f0b = *(const float2*)(pX0 + cn + 8);
            f1a = *(const float2*)(pX1 + cn);
            f1b = *(const float2*)(pX1 + cn + 8);
        }
        uint32_t ah[4], al[4];
        cvt2(c0a, ah[0], al[0]);
        cvt2(c1a, ah[1], al[1]);
        cvt2(c0b, ah[2], al[2]);
        cvt2(c1b, ah[3], al[3]);
        int kb = ks * 16 + brow;
#pragma unroll
        for (int nt = 0; nt < NT; nt++) {
            uint4 bv = *(const uint4*)&sB[nt * 8 * SWW + kb];
            mma16816(acc[nt], ah, bv.x, bv.y);
            mma16816(acc[nt], ah, bv.z, bv.w);
            mma16816(acc[nt], al, bv.x, bv.y);
        }
    }

    int row0 = bid * 128 + 16 * w + (lane >> 2);
    int row1 = row0 + 8;
    float asv0[4] = {0, 0, 0, 0}, adv0[4] = {0, 0, 0, 0};
    float asv1[4] = {0, 0, 0, 0}, adv1[4] = {0, 0, 0, 0};
#pragma unroll
    for (int nt = 0; nt < NT; nt++) {
        int c = nt * 8 + (lane & 3) * 2;
        float b0 = L1 ? g_bc[c] : 0.f, b1 = L1 ? g_bc[c + 1] : 0.f;
        float v0 = acc[nt][0] + b0, v1 = acc[nt][1] + b1;
        float v2 = acc[nt][2] + b0, v3 = acc[nt][3] + b1;
        int h = c >> CSH;
        float s0 = __ldg(a_src + c), s1 = __ldg(a_src + c + 1);
        float d0 = __ldg(a_dst + c), d1 = __ldg(a_dst + c + 1);
        asv0[h] = fmaf(v0, s0, fmaf(v1, s1, asv0[h]));
        adv0[h] = fmaf(v0, d0, fmaf(v1, d1, adv0[h]));
        asv1[h] = fmaf(v2, s0, fmaf(v3, s1, asv1[h]));
        adv1[h] = fmaf(v2, d0, fmaf(v3, d1, adv1[h]));
        if (row0 < n) *(float2*)&Hout[(size_t)row0 * NOUT + c] = make_float2(v0, v1);
        if (row1 < n) *(float2*)&Hout[(size_t)row1 * NOUT + c] = make_float2(v2, v3);
    }
#pragma unroll
    for (int o = 1; o <= 2; o <<= 1) {
#pragma unroll
        for (int h = 0; h < 4; h++) {
            asv0[h] += __shfl_xor_sync(0xffffffffu, asv0[h], o);
            adv0[h] += __shfl_xor_sync(0xffffffffu, adv0[h], o);
            asv1[h] += __shfl_xor_sync(0xffffffffu, asv1[h], o);
            adv1[h] += __shfl_xor_sync(0xffffffffu, adv1[h], o);
        }
    }
    if ((lane & 3) == 0) {
        if (row0 < n) {
            *(float4*)&as_out[row0 * 4] = make_float4(asv0[0], asv0[1], asv0[2], asv0[3]);
            *(float4*)&ad_out[row0 * 4] = make_float4(adv0[0], adv0[1], adv0[2], adv0[3]);
        }
        if (row1 < n) {
            *(float4*)&as_out[row1 * 4] = make_float4(asv1[0], asv1[1], asv1[2], asv1[3]);
            *(float4*)&ad_out[row1 * 4] = make_float4(adv1[0], adv1[1], adv1[2], adv1[3]);
        }
    }
}

// ---------------- layer-1 aggregation: warp per dst node, fused stream -----
__global__ void __launch_bounds__(256) k_aggr1(const float* __restrict__ b1, int n) {
    int warp = threadIdx.x >> 5, lane = threadIdx.x & 31;
    int node = blockIdx.x * 8 + warp;
    if (node >= n) return;
    int beg = g_off[node], end = g_off[node + 1];
    int h = lane >> 3, col = 4 * lane;
    float adv = g_ad1[node * 4 + h];
    float s = 0.f;
    float ax = 0.f, ay = 0.f, az = 0.f, aw = 0.f;

#pragma unroll 2
    for (int idx = beg; idx < end; idx += 4) {
        bool n1 = idx + 1 < end, n2 = idx + 2 < end, n3 = idx + 3 < end;
        int s0 = __ldg(&g_csrc[idx]);
        int s1 = n1 ? __ldg(&g_csrc[idx + 1]) : s0;
        int s2 = n2 ? __ldg(&g_csrc[idx + 2]) : s0;
        int s3 = n3 ? __ldg(&g_csrc[idx + 3]) : s0;
        float a0 = __ldg(&g_as1[s0 * 4 + h]);
        float a1 = __ldg(&g_as1[s1 * 4 + h]);
        float a2 = __ldg(&g_as1[s2 * 4 + h]);
        float a3 = __ldg(&g_as1[s3 * 4 + h]);
        float4 v0 = *(const float4*)&g_h1[(size_t)s0 * 128 + col];
        float4 v1 = *(const float4*)&g_h1[(size_t)s1 * 128 + col];
        float4 v2 = *(const float4*)&g_h1[(size_t)s2 * 128 + col];
        float4 v3 = *(const float4*)&g_h1[(size_t)s3 * 128 + col];
        float e0 = __expf(leaky02(a0 + adv));
        float e1 = n1 ? __expf(leaky02(a1 + adv)) : 0.f;
        float e2 = n2 ? __expf(leaky02(a2 + adv)) : 0.f;
        float e3 = n3 ? __expf(leaky02(a3 + adv)) : 0.f;
        s += (e0 + e1) + (e2 + e3);
        ax = fmaf(e0, v0.x, ax); ay = fmaf(e0, v0.y, ay);
        az = fmaf(e0, v0.z, az); aw = fmaf(e0, v0.w, aw);
        ax = fmaf(e1, v1.x, ax); ay = fmaf(e1, v1.y, ay);
        az = fmaf(e1, v1.z, az); aw = fmaf(e1, v1.w, aw);
        ax = fmaf(e2, v2.x, ax); ay = fmaf(e2, v2.y, ay);
        az = fmaf(e2, v2.z, az); aw = fmaf(e2, v2.w, aw);
        ax = fmaf(e3, v3.x, ax); ay = fmaf(e3, v3.y, ay);
        az = fmaf(e3, v3.z, az); aw = fmaf(e3, v3.w, aw);
    }
    float inv = 1.f / (s + 1e-16f);
    float4 bb = *(const float4*)&b1[col];
    float o0 = ax * inv + bb.x;
    float o1 = ay * inv + bb.y;
    float o2 = az * inv + bb.z;
    float o3 = aw * inv + bb.w;
    o0 = o0 > 0.f ? o0 : expm1f(o0);
    o1 = o1 > 0.f ? o1 : expm1f(o1);
    o2 = o2 > 0.f ? o2 : expm1f(o2);
    o3 = o3 > 0.f ? o3 : expm1f(o3);
    *(float4*)&g_y1[(size_t)node * 128 + col] = make_float4(o0, o1, o2, o3);
}

// ---------------- layer-2 aggregation + head-mean + log_softmax ------------
__global__ void __launch_bounds__(256) k_aggr2(const float* __restrict__ b2,
                                               float* __restrict__ out, int n) {
    int warp = threadIdx.x >> 5, lane = threadIdx.x & 31;
    int node = blockIdx.x * 8 + warp;
    if (node >= n) return;
    int beg = g_off[node], end = g_off[node + 1];
    int h = lane >> 3, col = 2 * lane;
    float adv = g_ad2[node * 4 + h];
    float s = 0.f, ax = 0.f, ay = 0.f;

#pragma unroll 2
    for (int idx = beg; idx < end; idx += 4) {
        bool n1 = idx + 1 < end, n2 = idx + 2 < end, n3 = idx + 3 < end;
        int s0 = __ldg(&g_csrc[idx]);
        int s1 = n1 ? __ldg(&g_csrc[idx + 1]) : s0;
        int s2 = n2 ? __ldg(&g_csrc[idx + 2]) : s0;
        int s3 = n3 ? __ldg(&g_csrc[idx + 3]) : s0;
        float a0 = __ldg(&g_as2[s0 * 4 + h]);
        float a1 = __ldg(&g_as2[s1 * 4 + h]);
        float a2 = __ldg(&g_as2[s2 * 4 + h]);
        float a3 = __ldg(&g_as2[s3 * 4 + h]);
        float2 v0 = *(const float2*)&g_h2[(size_t)s0 * 64 + col];
        float2 v1 = *(const float2*)&g_h2[(size_t)s1 * 64 + col];
        float2 v2 = *(const float2*)&g_h2[(size_t)s2 * 64 + col];
        float2 v3 = *(const float2*)&g_h2[(size_t)s3 * 64 + col];
        float e0 = __expf(leaky02(a0 + adv));
        float e1 = n1 ? __expf(leaky02(a1 + adv)) : 0.f;
        float e2 = n2 ? __expf(leaky02(a2 + adv)) : 0.f;
        float e3 = n3 ? __expf(leaky02(a3 + adv)) : 0.f;
        s += (e0 + e1) + (e2 + e3);
        ax = fmaf(e0, v0.x, ax); ay = fmaf(e0, v0.y, ay);
        ax = fmaf(e1, v1.x, ax); ay = fmaf(e1, v1.y, ay);
        ax = fmaf(e2, v2.x, ax); ay = fmaf(e2, v2.y, ay);
        ax = fmaf(e3, v3.x, ax); ay = fmaf(e3, v3.y, ay);
    }
    float inv = 1.f / (s + 1e-16f);
    float ox = ax * inv, oy = ay * inv;
    ox += __shfl_xor_sync(0xffffffffu, ox, 8);
    oy += __shfl_xor_sync(0xffffffffu, oy, 8);
    ox += __shfl_xor_sync(0xffffffffu, ox, 16);
    oy += __shfl_xor_sync(0xffffffffu, oy, 16);
    int c0 = 2 * (lane & 7);
    ox = ox * 0.25f + b2[c0];
    oy = oy * 0.25f + b2[c0 + 1];
    float mx = fmaxf(ox, oy);
#pragma unroll
    for (int o = 4; o; o >>= 1) mx = fmaxf(mx, __shfl_xor_sync(0xffffffffu, mx, o));
    float se = __expf(ox - mx) + __expf(oy - mx);
#pragma unroll
    for (int o = 4; o; o >>= 1) se += __shfl_xor_sync(0xffffffffu, se, o);
    float lse = mx + logf(se);
    if (lane < 8)
        *(float2*)&out[(size_t)node * 16 + c0] = make_float2(ox - lse, oy - lse);
}

// ---------------- launcher: capture-legal fork, CSR || prepW+GEMM1 ---------
extern "C" void kernel_launch(void* const* d_in, const int* in_sizes, int n_in,
                              void* d_out, int out_size) {
    const float* x = (const float*)d_in[0];
    const int* ei = (const int*)d_in[1];
    const float* Wemb = (const float*)d_in[2];
    const float* bemb = (const float*)d_in[3];
    const float* W1 = (const float*)d_in[4];
    const float* a_src1 = (const float*)d_in[5];
    const float* a_dst1 = (const float*)d_in[6];
    const float* b1 = (const float*)d_in[7];
    const float* W2 = (const float*)d_in[8];
    const float* a_src2 = (const float*)d_in[9];
    const float* a_dst2 = (const float*)d_in[10];
    const float* b2 = (const float*)d_in[11];
    float* out = (float*)d_out;

    int n = in_sizes[0] / 128;
    int e = in_sizes[1] / 2;
    if (n <= 0 || n > NMAX || e <= 0 || e > EMAX) return;
    const int* src = ei;
    const int* dst = ei + e;
    int nb = (n + 1023) / 1024;
    int nbg = (n + 127) / 128;

    // one-time side-stream + fork/join events (created on first, non-captured call)
    static cudaStream_t sB = nullptr;
    static cudaEvent_t evF = nullptr, evJ = nullptr;
    if (sB == nullptr) {
        cudaStreamCreateWithFlags(&sB, cudaStreamNonBlocking);
        cudaEventCreateWithFlags(&evF, cudaEventDisableTiming);
        cudaEventCreateWithFlags(&evJ, cudaEventDisableTiming);
    }

    int smem1 = 128 * SWW * 4;  // 73728
    int smem2 = 64 * SWW * 4;   // 36864
    cudaFuncSetAttribute(k_gemm_mma<128, true>,
                         cudaFuncAttributeMaxDynamicSharedMemorySize, smem1);
    cudaFuncSetAttribute(k_gemm_mma<64, false>,
                         cudaFuncAttributeMaxDynamicSharedMemorySize, smem2);

    // fork FIRST (empty) so the side stream joins the capture graph at t=0
    cudaEventRecord(evF, 0);
    cudaStreamWaitEvent(sB, evF, 0);

    // branch B (side stream): CSR build
    k_prepG<<<(n + 64 + 255) / 256, 256, 0, sB>>>(n);
    k_hist<<<(e + 255) / 256, 256, 0, sB>>>(dst, e);
    k_scan<<<nb, 1024, 0, sB>>>(n);
    k_scatter<<<(e + 255) / 256, 256, 0, sB>>>(src, dst, e);
    cudaEventRecord(evJ, sB);

    // branch A (main stream): weight prep + GEMM1
    int prepw_items = 128 * 128 + 64 * 128 + 128;
    k_prepW<<<(prepw_items + 255) / 256, 256>>>(Wemb, bemb, W1, W2);
    k_gemm_mma<128, true><<<nbg, 256, smem1>>>(x, a_src1, a_dst1, n);

    // join, then the dependent tail
    cudaStreamWaitEvent(0, evJ, 0);
    k_aggr1<<<(n + 7) / 8, 256>>>(b1, n);
    k_gemm_mma<64, false><<<nbg, 256, smem2>>>(nullptr, a_src2, a_dst2, n);
    k_aggr2<<<(n + 7) / 8, 256>>>(b2, out, n);
}

// round 14
// speedup vs baseline: 1.0594x; 1.0390x over previous
#include <cuda_runtime.h>
#include <cuda_bf16.h>
#include <math.h>
#include <cstdint>

static constexpr int NMAX = 50000;
static constexpr int EMAX = 800000;
static constexpr int SWW = 144;  // B row stride in words (128 data + 16 pad; 144%32==16)

// ---------------- scratch (device globals; no allocation allowed) ----------
__device__ __align__(16) float g_bc[128];                 // bemb @ W1
__device__ __align__(16) float g_h1[(size_t)NMAX * 128];  // layer1 pre-attn features
__device__ __align__(16) float g_y1[(size_t)NMAX * 128];  // elu(aggr1 + b1)
__device__ __align__(16) float g_h2[(size_t)NMAX * 64];   // layer2 pre-attn features
__device__ __align__(16) float g_as1[NMAX * 4];
__device__ __align__(16) float g_ad1[NMAX * 4];
__device__ __align__(16) float g_as2[NMAX * 4];
__device__ __align__(16) float g_ad2[NMAX * 4];
__device__ int g_deg[NMAX];
__device__ int g_cur[NMAX];
__device__ int g_off[NMAX + 1];
__device__ int g_csrc[EMAX];
__device__ unsigned g_lb[64];  // lookback state: flag(2b)<<30 | value
// B tiles, fragment-interleaved: per row (n), per ks (16 words):
//   word[ks*16 + cA*4 + {0,1,2,3}] = {hi(8ks+cA), hi(8ks+cA+4), lo(...), lo(...)}
__device__ __align__(16) uint32_t g_B1w[128 * SWW];  // Wc  (N=128,K=128)
__device__ __align__(16) uint32_t g_B2w[64 * SWW];   // W2  (N=64, K=128)

// ---------------- helpers ---------------------------------------------------
__device__ __forceinline__ void mma16816(float* d, const uint32_t* a, uint32_t b0,
                                         uint32_t b1) {
    asm volatile(
        "mma.sync.aligned.m16n8k16.row.col.f32.bf16.bf16.f32 "
        "{%0,%1,%2,%3}, {%4,%5,%6,%7}, {%8,%9}, {%0,%1,%2,%3};"
        : "+f"(d[0]), "+f"(d[1]), "+f"(d[2]), "+f"(d[3])
        : "r"(a[0]), "r"(a[1]), "r"(a[2]), "r"(a[3]), "r"(b0), "r"(b1));
}
__device__ __forceinline__ uint32_t pack_bf2(__nv_bfloat16 a, __nv_bfloat16 b) {
    return (uint32_t)*(unsigned short*)&a | ((uint32_t)*(unsigned short*)&b << 16);
}
__device__ __forceinline__ void cvt2(float2 f, uint32_t& h, uint32_t& l) {
    __nv_bfloat16 b0 = __float2bfloat16(f.x);
    __nv_bfloat16 b1 = __float2bfloat16(f.y);
    h = pack_bf2(b0, b1);
    l = pack_bf2(__float2bfloat16(f.x - __bfloat162float(b0)),
                 __float2bfloat16(f.y - __bfloat162float(b1)));
}
__device__ __forceinline__ float leaky02(float x) { return x > 0.f ? x : 0.2f * x; }
// short offset (within a row, in shorts) for element k of hi (slotbase 0) / lo (+2)
__device__ __forceinline__ int bslot(int k) {
    int p = k >> 1, ks = p >> 3, r = p & 7;
    int cAx = r & 3, slot = r >> 2;
    return (ks * 16 + cAx * 4 + slot) * 2 + (k & 1);
}

// ---------------- prepW: weights -> interleaved bf16 B tiles + bc ----------
__global__ void k_prepW(const float* __restrict__ Wemb, const float* __restrict__ bemb,
                        const float* __restrict__ W1, const float* __restrict__ W2) {
    int t = blockIdx.x * blockDim.x + threadIdx.x;
    if (t < 128 * 128) {
        int c = t & 127, k = t >> 7;
        float s = 0.f;
#pragma unroll
        for (int m = 0; m < 32; m++) s = fmaf(Wemb[k * 32 + m], W1[m * 128 + c], s);
        __nv_bfloat16 h = __float2bfloat16(s);
        __nv_bfloat16 l = __float2bfloat16(s - __bfloat162float(h));
        unsigned short* B = (unsigned short*)g_B1w;
        int so = bslot(k);
        B[c * SWW * 2 + so] = *(unsigned short*)&h;
        B[c * SWW * 2 + so + 4] = *(unsigned short*)&l;
    } else if (t < 128 * 128 + 64 * 128) {
        int u = t - 128 * 128;
        int c = u & 63, k = u >> 6;
        float s = W2[k * 64 + c];
        __nv_bfloat16 h = __float2bfloat16(s);
        __nv_bfloat16 l = __float2bfloat16(s - __bfloat162float(h));
        unsigned short* B = (unsigned short*)g_B2w;
        int so = bslot(k);
        B[c * SWW * 2 + so] = *(unsigned short*)&h;
        B[c * SWW * 2 + so + 4] = *(unsigned short*)&l;
    } else if (t < 128 * 128 + 64 * 128 + 128) {
        int c = t - (128 * 128 + 64 * 128);
        float s = 0.f;
#pragma unroll
        for (int m = 0; m < 32; m++) s = fmaf(bemb[m], W1[m * 128 + c], s);
        g_bc[c] = s;
    }
}

// ---------------- prepG: zero deg + lookback flags (CSR branch) ------------
__global__ void k_prepG(int n) {
    int t = blockIdx.x * blockDim.x + threadIdx.x;
    if (t < 64) g_lb[t] = 0u;
    int i = t - 64;
    if (i >= 0 && i < n) g_deg[i] = 0;
}

// ---------------- CSR build ------------------------------------------------
__global__ void k_hist(const int* __restrict__ dst, int e) {
    int i = blockIdx.x * blockDim.x + threadIdx.x;
    if (i < e) atomicAdd(&g_deg[dst[i]], 1);
}

// single-pass decoupled-lookback exclusive scan: g_deg -> g_off, g_cur
__global__ void __launch_bounds__(1024) k_scan(int n) {
    __shared__ int ws[32];
    __shared__ int sprefix;
    int b = blockIdx.x, t = threadIdx.x;
    int lane = t & 31, w = t >> 5;
    int i = b * 1024 + t;
    int v = (i < n) ? g_deg[i] : 0;
    int x = v;
#pragma unroll
    for (int o = 1; o < 32; o <<= 1) {
        int y = __shfl_up_sync(0xffffffffu, x, o);
        if (lane >= o) x += y;
    }
    if (lane == 31) ws[w] = x;
    __syncthreads();
    if (w == 0) {
        int s = ws[lane];
#pragma unroll
        for (int o = 1; o < 32; o <<= 1) {
            int y = __shfl_up_sync(0xffffffffu, s, o);
            if (lane >= o) s += y;
        }
        ws[lane] = s;
    }
    __syncthreads();
    if (t == 0) {
        unsigned total = (unsigned)ws[31];
        if (b == 0) {
            atomicExch(&g_lb[0], (2u << 30) | total);
            sprefix = 0;
        } else {
            atomicExch(&g_lb[b], (1u << 30) | total);
            unsigned pref = 0;
            int p = b - 1;
            while (true) {
                unsigned u = atomicOr(&g_lb[p], 0u);
                unsigned f = u >> 30;
                if (f == 0u) continue;
                pref += u & 0x3FFFFFFFu;
                if (f == 2u) break;
                p--;
            }
            atomicExch(&g_lb[b], (2u << 30) | (pref + total));
            sprefix = (int)pref;
        }
    }
    __syncthreads();
    int incl = sprefix + (w ? ws[w - 1] : 0) + x;
    if (i < n) {
        g_off[i + 1] = incl;
        g_cur[i] = incl - v;
    }
    if (i == 0) g_off[0] = 0;
}

__global__ void k_scatter(const int* __restrict__ src, const int* __restrict__ dst, int e) {
    int i = blockIdx.x * blockDim.x + threadIdx.x;
    if (i < e) {
        int p = atomicAdd(&g_cur[dst[i]], 1);
        g_csrc[p] = src[i];
    }
}

// ---------------- HMMA GEMM + attention epilogue ---------------------------
// C[128 x NOUT] per CTA; split-bf16 (hh + hl + lh). 8 warps x 16 rows. A
// converted in registers from global (L1-resident). B fragments via ONE
// LDS.128 per (ks, n-tile): interleaved layout, conflict-free (SWW%32==16).
template <int NOUT, bool L1>
__global__ void __launch_bounds__(256) k_gemm_mma(
    const float* __restrict__ Xin, const float* __restrict__ a_src,
    const float* __restrict__ a_dst, int n) {
    constexpr int NT = NOUT / 8;
    constexpr int CSH = (NOUT == 128) ? 5 : 4;
    constexpr int BT = NOUT * SWW;  // words
    extern __shared__ uint32_t smw[];
    uint32_t* sB = smw;

    int tid = threadIdx.x, w = tid >> 5, lane = tid & 31;
    int bid = blockIdx.x;
    const float* X = L1 ? Xin : (const float*)g_y1;
    const uint32_t* Bg = L1 ? g_B1w : g_B2w;
    float* Hout = L1 ? g_h1 : g_h2;
    float* as_out = L1 ? g_as1 : g_as2;
    float* ad_out = L1 ? g_ad1 : g_ad2;

    for (int i = tid; i < BT / 4; i += 256)
        ((float4*)sB)[i] = ((const float4*)Bg)[i];
    __syncthreads();

    int r0g = bid * 128 + 16 * w + (lane >> 2);
    const float* pX0 = X + (size_t)min(r0g, n - 1) * 128;
    const float* pX1 = X + (size_t)min(r0g + 8, n - 1) * 128;
    int cA = lane & 3;
    int brow = (lane >> 2) * SWW + cA * 4;

    float acc[NT][4];
#pragma unroll
    for (int t = 0; t < NT; t++)
#pragma unroll
        for (int j = 0; j < 4; j++) acc[t][j] = 0.f;

    // prefetch ks=0
    int c0 = 2 * cA;
    float2 f0a = *(const float2*)(pX0 + c0);
    float2 f0b = *(const float2*)(pX0 + c0 + 8);
    float2 f1a = *(const float2*)(pX1 + c0);
    float2 f1b = *(const float2*)(pX1 + c0 + 8);

#pragma unroll
    for (int ks = 0; ks < 8; ks++) {
        float2 c0a = f0a, c0b = f0b, c1a = f1a, c1b = f1b;
        if (ks < 7) {
            int cn = 2 * (8 * (ks + 1) + cA);
            f0a = *(const float2*)(pX0 + cn);
            f0b = *(const float2*)(pX0 + cn + 8);
            f1a = *(const float2*)(pX1 + cn);
            f1b = *(const float2*)(pX1 + cn + 8);
        }
        uint32_t ah[4], al[4];
        cvt2(c0a, ah[0], al[0]);
        cvt2(c1a, ah[1], al[1]);
        cvt2(c0b, ah[2], al[2]);
        cvt2(c1b, ah[3], al[3]);
        int kb = ks * 16 + brow;
#pragma unroll
        for (int nt = 0; nt < NT; nt++) {
            uint4 bv = *(const uint4*)&sB[nt * 8 * SWW + kb];
            mma16816(acc[nt], ah, bv.x, bv.y);
            mma16816(acc[nt], ah, bv.z, bv.w);
            mma16816(acc[nt], al, bv.x, bv.y);
        }
    }

    int row0 = bid * 128 + 16 * w + (lane >> 2);
    int row1 = row0 + 8;
    float asv0[4] = {0, 0, 0, 0}, adv0[4] = {0, 0, 0, 0};
    float asv1[4] = {0, 0, 0, 0}, adv1[4] = {0, 0, 0, 0};
#pragma unroll
    for (int nt = 0; nt < NT; nt++) {
        int c = nt * 8 + (lane & 3) * 2;
        float b0 = L1 ? g_bc[c] : 0.f, b1 = L1 ? g_bc[c + 1] : 0.f;
        float v0 = acc[nt][0] + b0, v1 = acc[nt][1] + b1;
        float v2 = acc[nt][2] + b0, v3 = acc[nt][3] + b1;
        int h = c >> CSH;
        float s0 = __ldg(a_src + c), s1 = __ldg(a_src + c + 1);
        float d0 = __ldg(a_dst + c), d1 = __ldg(a_dst + c + 1);
        asv0[h] = fmaf(v0, s0, fmaf(v1, s1, asv0[h]));
        adv0[h] = fmaf(v0, d0, fmaf(v1, d1, adv0[h]));
        asv1[h] = fmaf(v2, s0, fmaf(v3, s1, asv1[h]));
        adv1[h] = fmaf(v2, d0, fmaf(v3, d1, adv1[h]));
        if (row0 < n) *(float2*)&Hout[(size_t)row0 * NOUT + c] = make_float2(v0, v1);
        if (row1 < n) *(float2*)&Hout[(size_t)row1 * NOUT + c] = make_float2(v2, v3);
    }
#pragma unroll
    for (int o = 1; o <= 2; o <<= 1) {
#pragma unroll
        for (int h = 0; h < 4; h++) {
            asv0[h] += __shfl_xor_sync(0xffffffffu, asv0[h], o);
            adv0[h] += __shfl_xor_sync(0xffffffffu, adv0[h], o);
            asv1[h] += __shfl_xor_sync(0xffffffffu, asv1[h], o);
            adv1[h] += __shfl_xor_sync(0xffffffffu, adv1[h], o);
        }
    }
    if ((lane & 3) == 0) {
        if (row0 < n) {
            *(float4*)&as_out[row0 * 4] = make_float4(asv0[0], asv0[1], asv0[2], asv0[3]);
            *(float4*)&ad_out[row0 * 4] = make_float4(adv0[0], adv0[1], adv0[2], adv0[3]);
        }
        if (row1 < n) {
            *(float4*)&as_out[row1 * 4] = make_float4(asv1[0], asv1[1], asv1[2], asv1[3]);
            *(float4*)&ad_out[row1 * 4] = make_float4(adv1[0], adv1[1], adv1[2], adv1[3]);
        }
    }
}

// ---------------- layer-1 aggregation: warp per dst node, fused stream -----
__global__ void __launch_bounds__(256) k_aggr1(const float* __restrict__ b1, int n) {
    int warp = threadIdx.x >> 5, lane = threadIdx.x & 31;
    int node = blockIdx.x * 8 + warp;
    if (node >= n) return;
    int beg = g_off[node], end = g_off[node + 1];
    int h = lane >> 3, col = 4 * lane;
    float adv = g_ad1[node * 4 + h];
    float s = 0.f;
    float ax = 0.f, ay = 0.f, az = 0.f, aw = 0.f;

    for (int idx = beg; idx < end; idx += 4) {
        bool n1 = idx + 1 < end, n2 = idx + 2 < end, n3 = idx + 3 < end;
        int s0 = __ldg(&g_csrc[idx]);
        int s1 = n1 ? __ldg(&g_csrc[idx + 1]) : s0;
        int s2 = n2 ? __ldg(&g_csrc[idx + 2]) : s0;
        int s3 = n3 ? __ldg(&g_csrc[idx + 3]) : s0;
        float a0 = __ldg(&g_as1[s0 * 4 + h]);
        float a1 = __ldg(&g_as1[s1 * 4 + h]);
        float a2 = __ldg(&g_as1[s2 * 4 + h]);
        float a3 = __ldg(&g_as1[s3 * 4 + h]);
        float4 v0 = *(const float4*)&g_h1[(size_t)s0 * 128 + col];
        float4 v1 = *(const float4*)&g_h1[(size_t)s1 * 128 + col];
        float4 v2 = *(const float4*)&g_h1[(size_t)s2 * 128 + col];
        float4 v3 = *(const float4*)&g_h1[(size_t)s3 * 128 + col];
        float e0 = __expf(leaky02(a0 + adv));
        float e1 = n1 ? __expf(leaky02(a1 + adv)) : 0.f;
        float e2 = n2 ? __expf(leaky02(a2 + adv)) : 0.f;
        float e3 = n3 ? __expf(leaky02(a3 + adv)) : 0.f;
        s += (e0 + e1) + (e2 + e3);
        ax = fmaf(e0, v0.x, ax); ay = fmaf(e0, v0.y, ay);
        az = fmaf(e0, v0.z, az); aw = fmaf(e0, v0.w, aw);
        ax = fmaf(e1, v1.x, ax); ay = fmaf(e1, v1.y, ay);
        az = fmaf(e1, v1.z, az); aw = fmaf(e1, v1.w, aw);
        ax = fmaf(e2, v2.x, ax); ay = fmaf(e2, v2.y, ay);
        az = fmaf(e2, v2.z, az); aw = fmaf(e2, v2.w, aw);
        ax = fmaf(e3, v3.x, ax); ay = fmaf(e3, v3.y, ay);
        az = fmaf(e3, v3.z, az); aw = fmaf(e3, v3.w, aw);
    }
    float inv = 1.f / (s + 1e-16f);
    float4 bb = *(const float4*)&b1[col];
    float o0 = ax * inv + bb.x;
    float o1 = ay * inv + bb.y;
    float o2 = az * inv + bb.z;
    float o3 = aw * inv + bb.w;
    o0 = o0 > 0.f ? o0 : expm1f(o0);
    o1 = o1 > 0.f ? o1 : expm1f(o1);
    o2 = o2 > 0.f ? o2 : expm1f(o2);
    o3 = o3 > 0.f ? o3 : expm1f(o3);
    *(float4*)&g_y1[(size_t)node * 128 + col] = make_float4(o0, o1, o2, o3);
}

// ---------------- layer-2 aggregation + head-mean + log_softmax ------------
__global__ void __launch_bounds__(256) k_aggr2(const float* __restrict__ b2,
                                               float* __restrict__ out, int n) {
    int warp = threadIdx.x >> 5, lane = threadIdx.x & 31;
    int node = blockIdx.x * 8 + warp;
    if (node >= n) return;
    int beg = g_off[node], end = g_off[node + 1];
    int h = lane >> 3, col = 2 * lane;
    float adv = g_ad2[node * 4 + h];
    float s = 0.f, ax = 0.f, ay = 0.f;

    for (int idx = beg; idx < end; idx += 4) {
        bool n1 = idx + 1 < end, n2 = idx + 2 < end, n3 = idx + 3 < end;
        int s0 = __ldg(&g_csrc[idx]);
        int s1 = n1 ? __ldg(&g_csrc[idx + 1]) : s0;
        int s2 = n2 ? __ldg(&g_csrc[idx + 2]) : s0;
        int s3 = n3 ? __ldg(&g_csrc[idx + 3]) : s0;
        float a0 = __ldg(&g_as2[s0 * 4 + h]);
        float a1 = __ldg(&g_as2[s1 * 4 + h]);
        float a2 = __ldg(&g_as2[s2 * 4 + h]);
        float a3 = __ldg(&g_as2[s3 * 4 + h]);
        float2 v0 = *(const float2*)&g_h2[(size_t)s0 * 64 + col];
        float2 v1 = *(const float2*)&g_h2[(size_t)s1 * 64 + col];
        float2 v2 = *(const float2*)&g_h2[(size_t)s2 * 64 + col];
        float2 v3 = *(const float2*)&g_h2[(size_t)s3 * 64 + col];
        float e0 = __expf(leaky02(a0 + adv));
        float e1 = n1 ? __expf(leaky02(a1 + adv)) : 0.f;
        float e2 = n2 ? __expf(leaky02(a2 + adv)) : 0.f;
        float e3 = n3 ? __expf(leaky02(a3 + adv)) : 0.f;
        s += (e0 + e1) + (e2 + e3);
        ax = fmaf(e0, v0.x, ax); ay = fmaf(e0, v0.y, ay);
        ax = fmaf(e1, v1.x, ax); ay = fmaf(e1, v1.y, ay);
        ax = fmaf(e2, v2.x, ax); ay = fmaf(e2, v2.y, ay);
        ax = fmaf(e3, v3.x, ax); ay = fmaf(e3, v3.y, ay);
    }
    float inv = 1.f / (s + 1e-16f);
    float ox = ax * inv, oy = ay * inv;
    ox += __shfl_xor_sync(0xffffffffu, ox, 8);
    oy += __shfl_xor_sync(0xffffffffu, oy, 8);
    ox += __shfl_xor_sync(0xffffffffu, ox, 16);
    oy += __shfl_xor_sync(0xffffffffu, oy, 16);
    int c0 = 2 * (lane & 7);
    ox = ox * 0.25f + b2[c0];
    oy = oy * 0.25f + b2[c0 + 1];
    float mx = fmaxf(ox, oy);
#pragma unroll
    for (int o = 4; o; o >>= 1) mx = fmaxf(mx, __shfl_xor_sync(0xffffffffu, mx, o));
    float se = __expf(ox - mx) + __expf(oy - mx);
#pragma unroll
    for (int o = 4; o; o >>= 1) se += __shfl_xor_sync(0xffffffffu, se, o);
    float lse = mx + logf(se);
    if (lane < 8)
        *(float2*)&out[(size_t)node * 16 + c0] = make_float2(ox - lse, oy - lse);
}

// ---------------- launcher: capture-legal t=0 fork, CSR || prepW+GEMM1 -----
extern "C" void kernel_launch(void* const* d_in, const int* in_sizes, int n_in,
                              void* d_out, int out_size) {
    const float* x = (const float*)d_in[0];
    const int* ei = (const int*)d_in[1];
    const float* Wemb = (const float*)d_in[2];
    const float* bemb = (const float*)d_in[3];
    const float* W1 = (const float*)d_in[4];
    const float* a_src1 = (const float*)d_in[5];
    const float* a_dst1 = (const float*)d_in[6];
    const float* b1 = (const float*)d_in[7];
    const float* W2 = (const float*)d_in[8];
    const float* a_src2 = (const float*)d_in[9];
    const float* a_dst2 = (const float*)d_in[10];
    const float* b2 = (const float*)d_in[11];
    float* out = (float*)d_out;

    int n = in_sizes[0] / 128;
    int e = in_sizes[1] / 2;
    if (n <= 0 || n > NMAX || e <= 0 || e > EMAX) return;
    const int* src = ei;
    const int* dst = ei + e;
    int nb = (n + 1023) / 1024;
    int nbg = (n + 127) / 128;

    // one-time side-stream + fork/join events (created on first, non-captured call)
    static cudaStream_t sB = nullptr;
    static cudaEvent_t evF = nullptr, evJ = nullptr;
    if (sB == nullptr) {
        cudaStreamCreateWithFlags(&sB, cudaStreamNonBlocking);
        cudaEventCreateWithFlags(&evF, cudaEventDisableTiming);
        cudaEventCreateWithFlags(&evJ, cudaEventDisableTiming);
    }

    int smem1 = 128 * SWW * 4;  // 73728
    int smem2 = 64 * SWW * 4;   // 36864
    cudaFuncSetAttribute(k_gemm_mma<128, true>,
                         cudaFuncAttributeMaxDynamicSharedMemorySize, smem1);
    cudaFuncSetAttribute(k_gemm_mma<64, false>,
                         cudaFuncAttributeMaxDynamicSharedMemorySize, smem2);

    // fork FIRST (empty) so the side stream joins the capture graph at t=0
    cudaEventRecord(evF, 0);
    cudaStreamWaitEvent(sB, evF, 0);

    // branch B (side stream): CSR build
    k_prepG<<<(n + 64 + 255) / 256, 256, 0, sB>>>(n);
    k_hist<<<(e + 255) / 256, 256, 0, sB>>>(dst, e);
    k_scan<<<nb, 1024, 0, sB>>>(n);
    k_scatter<<<(e + 255) / 256, 256, 0, sB>>>(src, dst, e);
    cudaEventRecord(evJ, sB);

    // branch A (main stream): weight prep + GEMM1
    int prepw_items = 128 * 128 + 64 * 128 + 128;
    k_prepW<<<(prepw_items + 255) / 256, 256>>>(Wemb, bemb, W1, W2);
    k_gemm_mma<128, true><<<nbg, 256, smem1>>>(x, a_src1, a_dst1, n);

    // join, then the dependent tail
    cudaStreamWaitEvent(0, evJ, 0);
    k_aggr1<<<(n + 7) / 8, 256>>>(b1, n);
    k_gemm_mma<64, false><<<nbg, 256, smem2>>>(nullptr, a_src2, a_dst2, n);
    k_aggr2<<<(n + 7) / 8, 256>>>(b2, out, n);
}

// round 15
// speedup vs baseline: 1.0935x; 1.0322x over previous
#include <cuda_runtime.h>
#include <cuda_bf16.h>
#include <math.h>
#include <cstdint>

static constexpr int NMAX = 50000;
static constexpr int EMAX = 800000;
static constexpr int SWW = 144;  // B row stride in words (128 data + 16 pad; 144%32==16)

// ---------------- scratch (device globals; no allocation allowed) ----------
__device__ __align__(16) float g_bc[128];                 // bemb @ W1
__device__ __align__(16) unsigned short g_h1b[(size_t)NMAX * 128];  // bf16 h1 gather table
__device__ __align__(16) float g_y1[(size_t)NMAX * 128];            // elu(aggr1 + b1), fp32
__device__ __align__(16) unsigned short g_h2b[(size_t)NMAX * 64];   // bf16 h2 gather table
__device__ __align__(16) float g_as1[NMAX * 4];
__device__ __align__(16) float g_ad1[NMAX * 4];
__device__ __align__(16) float g_as2[NMAX * 4];
__device__ __align__(16) float g_ad2[NMAX * 4];
__device__ int g_deg[NMAX];
__device__ int g_cur[NMAX];
__device__ int g_off[NMAX + 1];
__device__ int g_csrc[EMAX];
__device__ unsigned g_lb[64];  // lookback state: flag(2b)<<30 | value
// B tiles, fragment-interleaved: per row (n), per ks (16 words):
//   word[ks*16 + cA*4 + {0,1,2,3}] = {hi(8ks+cA), hi(8ks+cA+4), lo(...), lo(...)}
__device__ __align__(16) uint32_t g_B1w[128 * SWW];  // Wc  (N=128,K=128)
__device__ __align__(16) uint32_t g_B2w[64 * SWW];   // W2  (N=64, K=128)

// ---------------- helpers ---------------------------------------------------
__device__ __forceinline__ void mma16816(float* d, const uint32_t* a, uint32_t b0,
                                         uint32_t b1) {
    asm volatile(
        "mma.sync.aligned.m16n8k16.row.col.f32.bf16.bf16.f32 "
        "{%0,%1,%2,%3}, {%4,%5,%6,%7}, {%8,%9}, {%0,%1,%2,%3};"
        : "+f"(d[0]), "+f"(d[1]), "+f"(d[2]), "+f"(d[3])
        : "r"(a[0]), "r"(a[1]), "r"(a[2]), "r"(a[3]), "r"(b0), "r"(b1));
}
__device__ __forceinline__ uint32_t pack_bf2(__nv_bfloat16 a, __nv_bfloat16 b) {
    return (uint32_t)*(unsigned short*)&a | ((uint32_t)*(unsigned short*)&b << 16);
}
__device__ __forceinline__ uint32_t pack_f2(float a, float b) {
    return pack_bf2(__float2bfloat16(a), __float2bfloat16(b));
}
__device__ __forceinline__ float2 bf2f(uint32_t u) {
    __nv_bfloat162 b = *(__nv_bfloat162*)&u;
    return __bfloat1622float2(b);
}
__device__ __forceinline__ void cvt2(float2 f, uint32_t& h, uint32_t& l) {
    __nv_bfloat16 b0 = __float2bfloat16(f.x);
    __nv_bfloat16 b1 = __float2bfloat16(f.y);
    h = pack_bf2(b0, b1);
    l = pack_bf2(__float2bfloat16(f.x - __bfloat162float(b0)),
                 __float2bfloat16(f.y - __bfloat162float(b1)));
}
__device__ __forceinline__ float leaky02(float x) { return x > 0.f ? x : 0.2f * x; }
// short offset (within a row, in shorts) for element k of hi (slotbase 0) / lo (+2)
__device__ __forceinline__ int bslot(int k) {
    int p = k >> 1, ks = p >> 3, r = p & 7;
    int cAx = r & 3, slot = r >> 2;
    return (ks * 16 + cAx * 4 + slot) * 2 + (k & 1);
}

// ---------------- prep: weights -> interleaved bf16 B tiles; bc; init ------
__global__ void k_prep(const float* __restrict__ Wemb, const float* __restrict__ bemb,
                       const float* __restrict__ W1, const float* __restrict__ W2,
                       int n) {
    int t = blockIdx.x * blockDim.x + threadIdx.x;
    if (t < 128 * 128) {
        int c = t & 127, k = t >> 7;
        float s = 0.f;
#pragma unroll
        for (int m = 0; m < 32; m++) s = fmaf(Wemb[k * 32 + m], W1[m * 128 + c], s);
        __nv_bfloat16 h = __float2bfloat16(s);
        __nv_bfloat16 l = __float2bfloat16(s - __bfloat162float(h));
        unsigned short* B = (unsigned short*)g_B1w;
        int so = bslot(k);
        B[c * SWW * 2 + so] = *(unsigned short*)&h;
        B[c * SWW * 2 + so + 4] = *(unsigned short*)&l;
    } else if (t < 128 * 128 + 64 * 128) {
        int u = t - 128 * 128;
        int c = u & 63, k = u >> 6;
        float s = W2[k * 64 + c];
        __nv_bfloat16 h = __float2bfloat16(s);
        __nv_bfloat16 l = __float2bfloat16(s - __bfloat162float(h));
        unsigned short* B = (unsigned short*)g_B2w;
        int so = bslot(k);
        B[c * SWW * 2 + so] = *(unsigned short*)&h;
        B[c * SWW * 2 + so + 4] = *(unsigned short*)&l;
    } else if (t < 128 * 128 + 64 * 128 + 128) {
        int c = t - (128 * 128 + 64 * 128);
        float s = 0.f;
#pragma unroll
        for (int m = 0; m < 32; m++) s = fmaf(bemb[m], W1[m * 128 + c], s);
        g_bc[c] = s;
    } else if (t < 128 * 128 + 64 * 128 + 128 + 64) {
        g_lb[t - (128 * 128 + 64 * 128 + 128)] = 0u;
    } else {
        int i = t - (128 * 128 + 64 * 128 + 128 + 64);
        if (i < n) g_deg[i] = 0;
    }
}

// ---------------- CSR build ------------------------------------------------
__global__ void k_hist(const int* __restrict__ dst, int e) {
    int i = blockIdx.x * blockDim.x + threadIdx.x;
    if (i < e) atomicAdd(&g_deg[dst[i]], 1);
}

// single-pass decoupled-lookback exclusive scan: g_deg -> g_off, g_cur
__global__ void __launch_bounds__(1024) k_scan(int n) {
    __shared__ int ws[32];
    __shared__ int sprefix;
    int b = blockIdx.x, t = threadIdx.x;
    int lane = t & 31, w = t >> 5;
    int i = b * 1024 + t;
    int v = (i < n) ? g_deg[i] : 0;
    int x = v;
#pragma unroll
    for (int o = 1; o < 32; o <<= 1) {
        int y = __shfl_up_sync(0xffffffffu, x, o);
        if (lane >= o) x += y;
    }
    if (lane == 31) ws[w] = x;
    __syncthreads();
    if (w == 0) {
        int s = ws[lane];
#pragma unroll
        for (int o = 1; o < 32; o <<= 1) {
            int y = __shfl_up_sync(0xffffffffu, s, o);
            if (lane >= o) s += y;
        }
        ws[lane] = s;
    }
    __syncthreads();
    if (t == 0) {
        unsigned total = (unsigned)ws[31];
        if (b == 0) {
            atomicExch(&g_lb[0], (2u << 30) | total);
            sprefix = 0;
        } else {
            atomicExch(&g_lb[b], (1u << 30) | total);
            unsigned pref = 0;
            int p = b - 1;
            while (true) {
                unsigned u = atomicOr(&g_lb[p], 0u);
                unsigned f = u >> 30;
                if (f == 0u) continue;
                pref += u & 0x3FFFFFFFu;
                if (f == 2u) break;
                p--;
            }
            atomicExch(&g_lb[b], (2u << 30) | (pref + total));
            sprefix = (int)pref;
        }
    }
    __syncthreads();
    int incl = sprefix + (w ? ws[w - 1] : 0) + x;
    if (i < n) {
        g_off[i + 1] = incl;
        g_cur[i] = incl - v;
    }
    if (i == 0) g_off[0] = 0;
}

__global__ void k_scatter(const int* __restrict__ src, const int* __restrict__ dst, int e) {
    int i = blockIdx.x * blockDim.x + threadIdx.x;
    if (i < e) {
        int p = atomicAdd(&g_cur[dst[i]], 1);
        g_csrc[p] = src[i];
    }
}

// ---------------- HMMA GEMM + attention epilogue ---------------------------
// C[128 x NOUT] per CTA; split-bf16 (hh + hl + lh). 8 warps x 16 rows.
// Feature output stored as bf16 (gather tables); dots/bias in fp32.
template <int NOUT, bool L1>
__global__ void __launch_bounds__(256) k_gemm_mma(
    const float* __restrict__ Xin, const float* __restrict__ a_src,
    const float* __restrict__ a_dst, int n) {
    constexpr int NT = NOUT / 8;
    constexpr int CSH = (NOUT == 128) ? 5 : 4;
    constexpr int BT = NOUT * SWW;  // words
    extern __shared__ uint32_t smw[];
    uint32_t* sB = smw;

    int tid = threadIdx.x, w = tid >> 5, lane = tid & 31;
    int bid = blockIdx.x;
    const float* X = L1 ? Xin : (const float*)g_y1;
    const uint32_t* Bg = L1 ? g_B1w : g_B2w;
    unsigned short* Hb = L1 ? g_h1b : g_h2b;
    float* as_out = L1 ? g_as1 : g_as2;
    float* ad_out = L1 ? g_ad1 : g_ad2;

    for (int i = tid; i < BT / 4; i += 256)
        ((float4*)sB)[i] = ((const float4*)Bg)[i];
    __syncthreads();

    int r0g = bid * 128 + 16 * w + (lane >> 2);
    const float* pX0 = X + (size_t)min(r0g, n - 1) * 128;
    const float* pX1 = X + (size_t)min(r0g + 8, n - 1) * 128;
    int cA = lane & 3;
    int brow = (lane >> 2) * SWW + cA * 4;

    float acc[NT][4];
#pragma unroll
    for (int t = 0; t < NT; t++)
#pragma unroll
        for (int j = 0; j < 4; j++) acc[t][j] = 0.f;

    // prefetch ks=0
    int c0 = 2 * cA;
    float2 f0a = *(const float2*)(pX0 + c0);
    float2 f0b = *(const float2*)(pX0 + c0 + 8);
    float2 f1a = *(const float2*)(pX1 + c0);
    float2 f1b = *(const float2*)(pX1 + c0 + 8);

#pragma unroll
    for (int ks = 0; ks < 8; ks++) {
        float2 c0a = f0a, c0b = f0b, c1a = f1a, c1b = f1b;
        if (ks < 7) {
            int cn = 2 * (8 * (ks + 1) + cA);
            f0a = *(const float2*)(pX0 + cn);
            f0b = *(const float2*)(pX0 + cn + 8);
            f1a = *(const float2*)(pX1 + cn);
            f1b = *(const float2*)(pX1 + cn + 8);
        }
        uint32_t ah[4], al[4];
        cvt2(c0a, ah[0], al[0]);
        cvt2(c1a, ah[1], al[1]);
        cvt2(c0b, ah[2], al[2]);
        cvt2(c1b, ah[3], al[3]);
        int kb = ks * 16 + brow;
#pragma unroll
        for (int nt = 0; nt < NT; nt++) {
            uint4 bv = *(const uint4*)&sB[nt * 8 * SWW + kb];
            mma16816(acc[nt], ah, bv.x, bv.y);
            mma16816(acc[nt], ah, bv.z, bv.w);
            mma16816(acc[nt], al, bv.x, bv.y);
        }
    }

    int row0 = bid * 128 + 16 * w + (lane >> 2);
    int row1 = row0 + 8;
    float asv0[4] = {0, 0, 0, 0}, adv0[4] = {0, 0, 0, 0};
    float asv1[4] = {0, 0, 0, 0}, adv1[4] = {0, 0, 0, 0};
#pragma unroll
    for (int nt = 0; nt < NT; nt++) {
        int c = nt * 8 + (lane & 3) * 2;
        float b0 = L1 ? g_bc[c] : 0.f, b1 = L1 ? g_bc[c + 1] : 0.f;
        float v0 = acc[nt][0] + b0, v1 = acc[nt][1] + b1;
        float v2 = acc[nt][2] + b0, v3 = acc[nt][3] + b1;
        int h = c >> CSH;
        float s0 = __ldg(a_src + c), s1 = __ldg(a_src + c + 1);
        float d0 = __ldg(a_dst + c), d1 = __ldg(a_dst + c + 1);
        asv0[h] = fmaf(v0, s0, fmaf(v1, s1, asv0[h]));
        adv0[h] = fmaf(v0, d0, fmaf(v1, d1, adv0[h]));
        asv1[h] = fmaf(v2, s0, fmaf(v3, s1, asv1[h]));
        adv1[h] = fmaf(v2, d0, fmaf(v3, d1, adv1[h]));
        if (row0 < n) *(uint32_t*)&Hb[(size_t)row0 * NOUT + c] = pack_f2(v0, v1);
        if (row1 < n) *(uint32_t*)&Hb[(size_t)row1 * NOUT + c] = pack_f2(v2, v3);
    }
#pragma unroll
    for (int o = 1; o <= 2; o <<= 1) {
#pragma unroll
        for (int h = 0; h < 4; h++) {
            asv0[h] += __shfl_xor_sync(0xffffffffu, asv0[h], o);
            adv0[h] += __shfl_xor_sync(0xffffffffu, adv0[h], o);
            asv1[h] += __shfl_xor_sync(0xffffffffu, asv1[h], o);
            adv1[h] += __shfl_xor_sync(0xffffffffu, adv1[h], o);
        }
    }
    if ((lane & 3) == 0) {
        if (row0 < n) {
            *(float4*)&as_out[row0 * 4] = make_float4(asv0[0], asv0[1], asv0[2], asv0[3]);
            *(float4*)&ad_out[row0 * 4] = make_float4(adv0[0], adv0[1], adv0[2], adv0[3]);
        }
        if (row1 < n) {
            *(float4*)&as_out[row1 * 4] = make_float4(asv1[0], asv1[1], asv1[2], asv1[3]);
            *(float4*)&ad_out[row1 * 4] = make_float4(adv1[0], adv1[1], adv1[2], adv1[3]);
        }
    }
}

// ---------------- layer-1 aggregation: warp per dst node, bf16 gather ------
__global__ void __launch_bounds__(256) k_aggr1(const float* __restrict__ b1, int n) {
    int warp = threadIdx.x >> 5, lane = threadIdx.x & 31;
    int node = blockIdx.x * 8 + warp;
    if (node >= n) return;
    int beg = g_off[node], end = g_off[node + 1];
    int h = lane >> 3, col = 4 * lane;
    float adv = g_ad1[node * 4 + h];
    float s = 0.f;
    float ax = 0.f, ay = 0.f, az = 0.f, aw = 0.f;

    for (int idx = beg; idx < end; idx += 4) {
        bool n1 = idx + 1 < end, n2 = idx + 2 < end, n3 = idx + 3 < end;
        int s0 = __ldg(&g_csrc[idx]);
        int s1 = n1 ? __ldg(&g_csrc[idx + 1]) : s0;
        int s2 = n2 ? __ldg(&g_csrc[idx + 2]) : s0;
        int s3 = n3 ? __ldg(&g_csrc[idx + 3]) : s0;
        float a0 = __ldg(&g_as1[s0 * 4 + h]);
        float a1 = __ldg(&g_as1[s1 * 4 + h]);
        float a2 = __ldg(&g_as1[s2 * 4 + h]);
        float a3 = __ldg(&g_as1[s3 * 4 + h]);
        uint2 u0 = *(const uint2*)&g_h1b[(size_t)s0 * 128 + col];
        uint2 u1 = *(const uint2*)&g_h1b[(size_t)s1 * 128 + col];
        uint2 u2 = *(const uint2*)&g_h1b[(size_t)s2 * 128 + col];
        uint2 u3 = *(const uint2*)&g_h1b[(size_t)s3 * 128 + col];
        float e0 = __expf(leaky02(a0 + adv));
        float e1 = n1 ? __expf(leaky02(a1 + adv)) : 0.f;
        float e2 = n2 ? __expf(leaky02(a2 + adv)) : 0.f;
        float e3 = n3 ? __expf(leaky02(a3 + adv)) : 0.f;
        s += (e0 + e1) + (e2 + e3);
        float2 p;
        p = bf2f(u0.x); ax = fmaf(e0, p.x, ax); ay = fmaf(e0, p.y, ay);
        p = bf2f(u0.y); az = fmaf(e0, p.x, az); aw = fmaf(e0, p.y, aw);
        p = bf2f(u1.x); ax = fmaf(e1, p.x, ax); ay = fmaf(e1, p.y, ay);
        p = bf2f(u1.y); az = fmaf(e1, p.x, az); aw = fmaf(e1, p.y, aw);
        p = bf2f(u2.x); ax = fmaf(e2, p.x, ax); ay = fmaf(e2, p.y, ay);
        p = bf2f(u2.y); az = fmaf(e2, p.x, az); aw = fmaf(e2, p.y, aw);
        p = bf2f(u3.x); ax = fmaf(e3, p.x, ax); ay = fmaf(e3, p.y, ay);
        p = bf2f(u3.y); az = fmaf(e3, p.x, az); aw = fmaf(e3, p.y, aw);
    }
    float inv = 1.f / (s + 1e-16f);
    float4 bb = *(const float4*)&b1[col];
    float o0 = ax * inv + bb.x;
    float o1 = ay * inv + bb.y;
    float o2 = az * inv + bb.z;
    float o3 = aw * inv + bb.w;
    o0 = o0 > 0.f ? o0 : expm1f(o0);
    o1 = o1 > 0.f ? o1 : expm1f(o1);
    o2 = o2 > 0.f ? o2 : expm1f(o2);
    o3 = o3 > 0.f ? o3 : expm1f(o3);
    *(float4*)&g_y1[(size_t)node * 128 + col] = make_float4(o0, o1, o2, o3);
}

// ---------------- layer-2 aggregation + head-mean + log_softmax ------------
__global__ void __launch_bounds__(256) k_aggr2(const float* __restrict__ b2,
                                               float* __restrict__ out, int n) {
    int warp = threadIdx.x >> 5, lane = threadIdx.x & 31;
    int node = blockIdx.x * 8 + warp;
    if (node >= n) return;
    int beg = g_off[node], end = g_off[node + 1];
    int h = lane >> 3, col = 2 * lane;
    float adv = g_ad2[node * 4 + h];
    float s = 0.f, ax = 0.f, ay = 0.f;

    for (int idx = beg; idx < end; idx += 4) {
        bool n1 = idx + 1 < end, n2 = idx + 2 < end, n3 = idx + 3 < end;
        int s0 = __ldg(&g_csrc[idx]);
        int s1 = n1 ? __ldg(&g_csrc[idx + 1]) : s0;
        int s2 = n2 ? __ldg(&g_csrc[idx + 2]) : s0;
        int s3 = n3 ? __ldg(&g_csrc[idx + 3]) : s0;
        float a0 = __ldg(&g_as2[s0 * 4 + h]);
        float a1 = __ldg(&g_as2[s1 * 4 + h]);
        float a2 = __ldg(&g_as2[s2 * 4 + h]);
        float a3 = __ldg(&g_as2[s3 * 4 + h]);
        uint32_t u0 = *(const uint32_t*)&g_h2b[(size_t)s0 * 64 + col];
        uint32_t u1 = *(const uint32_t*)&g_h2b[(size_t)s1 * 64 + col];
        uint32_t u2 = *(const uint32_t*)&g_h2b[(size_t)s2 * 64 + col];
        uint32_t u3 = *(const uint32_t*)&g_h2b[(size_t)s3 * 64 + col];
        float e0 = __expf(leaky02(a0 + adv));
        float e1 = n1 ? __expf(leaky02(a1 + adv)) : 0.f;
        float e2 = n2 ? __expf(leaky02(a2 + adv)) : 0.f;
        float e3 = n3 ? __expf(leaky02(a3 + adv)) : 0.f;
        s += (e0 + e1) + (e2 + e3);
        float2 p;
        p = bf2f(u0); ax = fmaf(e0, p.x, ax); ay = fmaf(e0, p.y, ay);
        p = bf2f(u1); ax = fmaf(e1, p.x, ax); ay = fmaf(e1, p.y, ay);
        p = bf2f(u2); ax = fmaf(e2, p.x, ax); ay = fmaf(e2, p.y, ay);
        p = bf2f(u3); ax = fmaf(e3, p.x, ax); ay = fmaf(e3, p.y, ay);
    }
    float inv = 1.f / (s + 1e-16f);
    float ox = ax * inv, oy = ay * inv;
    ox += __shfl_xor_sync(0xffffffffu, ox, 8);
    oy += __shfl_xor_sync(0xffffffffu, oy, 8);
    ox += __shfl_xor_sync(0xffffffffu, ox, 16);
    oy += __shfl_xor_sync(0xffffffffu, oy, 16);
    int c0 = 2 * (lane & 7);
    ox = ox * 0.25f + b2[c0];
    oy = oy * 0.25f + b2[c0 + 1];
    float mx = fmaxf(ox, oy);
#pragma unroll
    for (int o = 4; o; o >>= 1) mx = fmaxf(mx, __shfl_xor_sync(0xffffffffu, mx, o));
    float se = __expf(ox - mx) + __expf(oy - mx);
#pragma unroll
    for (int o = 4; o; o >>= 1) se += __shfl_xor_sync(0xffffffffu, se, o);
    float lse = mx + logf(se);
    if (lane < 8)
        *(float2*)&out[(size_t)node * 16 + c0] = make_float2(ox - lse, oy - lse);
}

// ---------------- launcher: R10 schedule (prep, fork CSR || GEMM1) ---------
extern "C" void kernel_launch(void* const* d_in, const int* in_sizes, int n_in,
                              void* d_out, int out_size) {
    const float* x = (const float*)d_in[0];
    const int* ei = (const int*)d_in[1];
    const float* Wemb = (const float*)d_in[2];
    const float* bemb = (const float*)d_in[3];
    const float* W1 = (const float*)d_in[4];
    const float* a_src1 = (const float*)d_in[5];
    const float* a_dst1 = (const float*)d_in[6];
    const float* b1 = (const float*)d_in[7];
    const float* W2 = (const float*)d_in[8];
    const float* a_src2 = (const float*)d_in[9];
    const float* a_dst2 = (const float*)d_in[10];
    const float* b2 = (const float*)d_in[11];
    float* out = (float*)d_out;

    int n = in_sizes[0] / 128;
    int e = in_sizes[1] / 2;
    if (n <= 0 || n > NMAX || e <= 0 || e > EMAX) return;
    const int* src = ei;
    const int* dst = ei + e;
    int nb = (n + 1023) / 1024;
    int nbg = (n + 127) / 128;

    // one-time side-stream + fork/join events (created on first, non-captured call)
    static cudaStream_t sB = nullptr;
    static cudaEvent_t evF = nullptr, evJ = nullptr;
    if (sB == nullptr) {
        cudaStreamCreateWithFlags(&sB, cudaStreamNonBlocking);
        cudaEventCreateWithFlags(&evF, cudaEventDisableTiming);
        cudaEventCreateWithFlags(&evJ, cudaEventDisableTiming);
    }

    int smem1 = 128 * SWW * 4;  // 73728
    int smem2 = 64 * SWW * 4;   // 36864
    cudaFuncSetAttribute(k_gemm_mma<128, true>,
                         cudaFuncAttributeMaxDynamicSharedMemorySize, smem1);
    cudaFuncSetAttribute(k_gemm_mma<64, false>,
                         cudaFuncAttributeMaxDynamicSharedMemorySize, smem2);

    int prep_items = 128 * 128 + 64 * 128 + 128 + 64 + n;

    // main stream: prep, then fork
    k_prep<<<(prep_items + 255) / 256, 256>>>(Wemb, bemb, W1, W2, n);
    cudaEventRecord(evF, 0);

    // branch B (side stream): CSR build
    cudaStreamWaitEvent(sB, evF, 0);
    k_hist<<<(e + 255) / 256, 256, 0, sB>>>(dst, e);
    k_scan<<<nb, 1024, 0, sB>>>(n);
    k_scatter<<<(e + 255) / 256, 256, 0, sB>>>(src, dst, e);
    cudaEventRecord(evJ, sB);

    // branch A (main stream): GEMM1 overlaps the CSR build
    k_gemm_mma<128, true><<<nbg, 256, smem1>>>(x, a_src1, a_dst1, n);

    // join, then the dependent tail
    cudaStreamWaitEvent(0, evJ, 0);
    k_aggr1<<<(n + 7) / 8, 256>>>(b1, n);
    k_gemm_mma<64, false><<<nbg, 256, smem2>>>(nullptr, a_src2, a_dst2, n);
    k_aggr2<<<(n + 7) / 8, 256>>>(b2, out, n);
}

// round 16
// speedup vs baseline: 1.1225x; 1.0265x over previous
#include <cuda_runtime.h>
#include <cuda_bf16.h>
#include <math.h>
#include <cstdint>

static constexpr int NMAX = 50000;
static constexpr int EMAX = 800000;
static constexpr int SWW = 144;  // B row stride in words (128 data + 16 pad; 144%32==16)
static constexpr int PGRP = 222; // persistent tile groups (444 CTAs = 3/SM x 148)

// ---------------- scratch (device globals; no allocation allowed) ----------
__device__ __align__(16) float g_bc[128];                 // bemb @ W1
__device__ __align__(16) unsigned short g_h1b[(size_t)NMAX * 128];  // bf16 h1 gather table
__device__ __align__(16) float g_y1[(size_t)NMAX * 128];            // elu(aggr1 + b1), fp32
__device__ __align__(16) unsigned short g_h2b[(size_t)NMAX * 64];   // bf16 h2 gather table
__device__ __align__(16) float g_as1[NMAX * 4];
__device__ __align__(16) float g_ad1[NMAX * 4];
__device__ __align__(16) float g_as2[NMAX * 4];
__device__ __align__(16) float g_ad2[NMAX * 4];
__device__ int g_deg[NMAX];
__device__ int g_cur[NMAX];
__device__ int g_off[NMAX + 1];
__device__ int g_csrc[EMAX];
__device__ unsigned g_lb[64];  // lookback state: flag(2b)<<30 | value
// B tiles, fragment-interleaved: per row (n), per ks (16 words):
//   word[ks*16 + cA*4 + {0,1,2,3}] = {hi(8ks+cA), hi(8ks+cA+4), lo(...), lo(...)}
__device__ __align__(16) uint32_t g_B1w[128 * SWW];  // Wc  (N=128,K=128)
__device__ __align__(16) uint32_t g_B2w[64 * SWW];   // W2  (N=64, K=128)

// ---------------- helpers ---------------------------------------------------
__device__ __forceinline__ void mma16816(float* d, const uint32_t* a, uint32_t b0,
                                         uint32_t b1) {
    asm volatile(
        "mma.sync.aligned.m16n8k16.row.col.f32.bf16.bf16.f32 "
        "{%0,%1,%2,%3}, {%4,%5,%6,%7}, {%8,%9}, {%0,%1,%2,%3};"
        : "+f"(d[0]), "+f"(d[1]), "+f"(d[2]), "+f"(d[3])
        : "r"(a[0]), "r"(a[1]), "r"(a[2]), "r"(a[3]), "r"(b0), "r"(b1));
}
__device__ __forceinline__ uint32_t pack_bf2(__nv_bfloat16 a, __nv_bfloat16 b) {
    return (uint32_t)*(unsigned short*)&a | ((uint32_t)*(unsigned short*)&b << 16);
}
__device__ __forceinline__ uint32_t pack_f2(float a, float b) {
    return pack_bf2(__float2bfloat16(a), __float2bfloat16(b));
}
__device__ __forceinline__ float2 bf2f(uint32_t u) {
    __nv_bfloat162 b = *(__nv_bfloat162*)&u;
    return __bfloat1622float2(b);
}
__device__ __forceinline__ void cvt2(float2 f, uint32_t& h, uint32_t& l) {
    __nv_bfloat16 b0 = __float2bfloat16(f.x);
    __nv_bfloat16 b1 = __float2bfloat16(f.y);
    h = pack_bf2(b0, b1);
    l = pack_bf2(__float2bfloat16(f.x - __bfloat162float(b0)),
                 __float2bfloat16(f.y - __bfloat162float(b1)));
}
__device__ __forceinline__ float leaky02(float x) { return x > 0.f ? x : 0.2f * x; }
// short offset (within a row, in shorts) for element k of hi (slotbase 0) / lo (+2)
__device__ __forceinline__ int bslot(int k) {
    int p = k >> 1, ks = p >> 3, r = p & 7;
    int cAx = r & 3, slot = r >> 2;
    return (ks * 16 + cAx * 4 + slot) * 2 + (k & 1);
}

// ---------------- prep: weights -> interleaved bf16 B tiles; bc; init ------
__global__ void k_prep(const float* __restrict__ Wemb, const float* __restrict__ bemb,
                       const float* __restrict__ W1, const float* __restrict__ W2,
                       int n) {
    int t = blockIdx.x * blockDim.x + threadIdx.x;
    if (t < 128 * 128) {
        int c = t & 127, k = t >> 7;
        float s = 0.f;
#pragma unroll
        for (int m = 0; m < 32; m++) s = fmaf(Wemb[k * 32 + m], W1[m * 128 + c], s);
        __nv_bfloat16 h = __float2bfloat16(s);
        __nv_bfloat16 l = __float2bfloat16(s - __bfloat162float(h));
        unsigned short* B = (unsigned short*)g_B1w;
        int so = bslot(k);
        B[c * SWW * 2 + so] = *(unsigned short*)&h;
        B[c * SWW * 2 + so + 4] = *(unsigned short*)&l;
    } else if (t < 128 * 128 + 64 * 128) {
        int u = t - 128 * 128;
        int c = u & 63, k = u >> 6;
        float s = W2[k * 64 + c];
        __nv_bfloat16 h = __float2bfloat16(s);
        __nv_bfloat16 l = __float2bfloat16(s - __bfloat162float(h));
        unsigned short* B = (unsigned short*)g_B2w;
        int so = bslot(k);
        B[c * SWW * 2 + so] = *(unsigned short*)&h;
        B[c * SWW * 2 + so + 4] = *(unsigned short*)&l;
    } else if (t < 128 * 128 + 64 * 128 + 128) {
        int c = t - (128 * 128 + 64 * 128);
        float s = 0.f;
#pragma unroll
        for (int m = 0; m < 32; m++) s = fmaf(bemb[m], W1[m * 128 + c], s);
        g_bc[c] = s;
    } else if (t < 128 * 128 + 64 * 128 + 128 + 64) {
        g_lb[t - (128 * 128 + 64 * 128 + 128)] = 0u;
    } else {
        int i = t - (128 * 128 + 64 * 128 + 128 + 64);
        if (i < n) g_deg[i] = 0;
    }
}

// ---------------- CSR build ------------------------------------------------
__global__ void k_hist(const int* __restrict__ dst, int e) {
    int i = blockIdx.x * blockDim.x + threadIdx.x;
    if (i < e) atomicAdd(&g_deg[dst[i]], 1);
}

// single-pass decoupled-lookback exclusive scan: g_deg -> g_off, g_cur
__global__ void __launch_bounds__(1024) k_scan(int n) {
    __shared__ int ws[32];
    __shared__ int sprefix;
    int b = blockIdx.x, t = threadIdx.x;
    int lane = t & 31, w = t >> 5;
    int i = b * 1024 + t;
    int v = (i < n) ? g_deg[i] : 0;
    int x = v;
#pragma unroll
    for (int o = 1; o < 32; o <<= 1) {
        int y = __shfl_up_sync(0xffffffffu, x, o);
        if (lane >= o) x += y;
    }
    if (lane == 31) ws[w] = x;
    __syncthreads();
    if (w == 0) {
        int s = ws[lane];
#pragma unroll
        for (int o = 1; o < 32; o <<= 1) {
            int y = __shfl_up_sync(0xffffffffu, s, o);
            if (lane >= o) s += y;
        }
        ws[lane] = s;
    }
    __syncthreads();
    if (t == 0) {
        unsigned total = (unsigned)ws[31];
        if (b == 0) {
            atomicExch(&g_lb[0], (2u << 30) | total);
            sprefix = 0;
        } else {
            atomicExch(&g_lb[b], (1u << 30) | total);
            unsigned pref = 0;
            int p = b - 1;
            while (true) {
                unsigned u = atomicOr(&g_lb[p], 0u);
                unsigned f = u >> 30;
                if (f == 0u) continue;
                pref += u & 0x3FFFFFFFu;
                if (f == 2u) break;
                p--;
            }
            atomicExch(&g_lb[b], (2u << 30) | (pref + total));
            sprefix = (int)pref;
        }
    }
    __syncthreads();
    int incl = sprefix + (w ? ws[w - 1] : 0) + x;
    if (i < n) {
        g_off[i + 1] = incl;
        g_cur[i] = incl - v;
    }
    if (i == 0) g_off[0] = 0;
}

__global__ void k_scatter(const int* __restrict__ src, const int* __restrict__ dst, int e) {
    int i = blockIdx.x * blockDim.x + threadIdx.x;
    if (i < e) {
        int p = atomicAdd(&g_cur[dst[i]], 1);
        g_csrc[p] = src[i];
    }
}

// ---------------- persistent split-N HMMA GEMM + attention epilogue --------
// Each CTA owns one N-half (CH = NOUT/2 cols = 2 heads), stages its half-B
// ONCE, then grid-strides over 128-row tiles. acc = CH/8*4 regs -> 3 CTAs/SM.
template <int NOUT, bool L1>
__global__ void __launch_bounds__(256, 3) k_gemm_mma(
    const float* __restrict__ Xin, const float* __restrict__ a_src,
    const float* __restrict__ a_dst, int n, int nbg) {
    constexpr int CH = NOUT / 2;
    constexpr int NT = CH / 8;
    constexpr int CSH = (NOUT == 128) ? 5 : 4;
    constexpr int BT = CH * SWW;  // words (half tile)
    extern __shared__ uint32_t smw[];
    uint32_t* sB = smw;

    int tid = threadIdx.x, w = tid >> 5, lane = tid & 31;
    int ch = blockIdx.x & 1;        // column half
    int tg = blockIdx.x >> 1;       // tile group 0..PGRP-1
    const float* X = L1 ? Xin : (const float*)g_y1;
    const uint32_t* Bg = (L1 ? g_B1w : g_B2w) + ch * CH * SWW;
    unsigned short* Hb = L1 ? g_h1b : g_h2b;
    float* as_out = L1 ? g_as1 : g_as2;
    float* ad_out = L1 ? g_ad1 : g_ad2;

    for (int i = tid; i < BT / 4; i += 256)
        ((float4*)sB)[i] = ((const float4*)Bg)[i];
    __syncthreads();

    int cA = lane & 3;
    int brow = (lane >> 2) * SWW + cA * 4;
    int c0 = 2 * cA;

    for (int tile = tg; tile < nbg; tile += PGRP) {
        int r0g = tile * 128 + 16 * w + (lane >> 2);
        const float* pX0 = X + (size_t)min(r0g, n - 1) * 128;
        const float* pX1 = X + (size_t)min(r0g + 8, n - 1) * 128;

        float acc[NT][4];
#pragma unroll
        for (int t = 0; t < NT; t++)
#pragma unroll
            for (int j = 0; j < 4; j++) acc[t][j] = 0.f;

        // prefetch ks=0
        float2 f0a = *(const float2*)(pX0 + c0);
        float2 f0b = *(const float2*)(pX0 + c0 + 8);
        float2 f1a = *(const float2*)(pX1 + c0);
        float2 f1b = *(const float2*)(pX1 + c0 + 8);

#pragma unroll
        for (int ks = 0; ks < 8; ks++) {
            float2 c0a = f0a, c0b = f0b, c1a = f1a, c1b = f1b;
            if (ks < 7) {
                int cn = 2 * (8 * (ks + 1) + cA);
                f0a = *(const float2*)(pX0 + cn);
                f0b = *(const float2*)(pX0 + cn + 8);
                f1a = *(const float2*)(pX1 + cn);
                f1b = *(const float2*)(pX1 + cn + 8);
            }
            uint32_t ah[4], al[4];
            cvt2(c0a, ah[0], al[0]);
            cvt2(c1a, ah[1], al[1]);
            cvt2(c0b, ah[2], al[2]);
            cvt2(c1b, ah[3], al[3]);
            int kb = ks * 16 + brow;
#pragma unroll
            for (int nt = 0; nt < NT; nt++) {
                uint4 bv = *(const uint4*)&sB[nt * 8 * SWW + kb];
                mma16816(acc[nt], ah, bv.x, bv.y);
                mma16816(acc[nt], ah, bv.z, bv.w);
                mma16816(acc[nt], al, bv.x, bv.y);
            }
        }

        int row0 = r0g;
        int row1 = r0g + 8;
        float asv0[2] = {0, 0}, adv0[2] = {0, 0};
        float asv1[2] = {0, 0}, adv1[2] = {0, 0};
#pragma unroll
        for (int nt = 0; nt < NT; nt++) {
            int cg = ch * CH + nt * 8 + (lane & 3) * 2;  // global col
            float b0 = L1 ? g_bc[cg] : 0.f, b1 = L1 ? g_bc[cg + 1] : 0.f;
            float v0 = acc[nt][0] + b0, v1 = acc[nt][1] + b1;
            float v2 = acc[nt][2] + b0, v3 = acc[nt][3] + b1;
            int hl = (cg >> CSH) & 1;  // head within half
            float s0 = __ldg(a_src + cg), s1 = __ldg(a_src + cg + 1);
            float d0 = __ldg(a_dst + cg), d1 = __ldg(a_dst + cg + 1);
            asv0[hl] = fmaf(v0, s0, fmaf(v1, s1, asv0[hl]));
            adv0[hl] = fmaf(v0, d0, fmaf(v1, d1, adv0[hl]));
            asv1[hl] = fmaf(v2, s0, fmaf(v3, s1, asv1[hl]));
            adv1[hl] = fmaf(v2, d0, fmaf(v3, d1, adv1[hl]));
            if (row0 < n) *(uint32_t*)&Hb[(size_t)row0 * NOUT + cg] = pack_f2(v0, v1);
            if (row1 < n) *(uint32_t*)&Hb[(size_t)row1 * NOUT + cg] = pack_f2(v2, v3);
        }
#pragma unroll
        for (int o = 1; o <= 2; o <<= 1) {
#pragma unroll
            for (int hl = 0; hl < 2; hl++) {
                asv0[hl] += __shfl_xor_sync(0xffffffffu, asv0[hl], o);
                adv0[hl] += __shfl_xor_sync(0xffffffffu, adv0[hl], o);
                asv1[hl] += __shfl_xor_sync(0xffffffffu, asv1[hl], o);
                adv1[hl] += __shfl_xor_sync(0xffffffffu, adv1[hl], o);
            }
        }
        if ((lane & 3) == 0) {
            int hb = ch * 2;
            if (row0 < n) {
                *(float2*)&as_out[row0 * 4 + hb] = make_float2(asv0[0], asv0[1]);
                *(float2*)&ad_out[row0 * 4 + hb] = make_float2(adv0[0], adv0[1]);
            }
            if (row1 < n) {
                *(float2*)&as_out[row1 * 4 + hb] = make_float2(asv1[0], asv1[1]);
                *(float2*)&ad_out[row1 * 4 + hb] = make_float2(adv1[0], adv1[1]);
            }
        }
    }
}

// ---------------- layer-1 aggregation: warp per dst node, bf16 gather ------
__global__ void __launch_bounds__(256) k_aggr1(const float* __restrict__ b1, int n) {
    int warp = threadIdx.x >> 5, lane = threadIdx.x & 31;
    int node = blockIdx.x * 8 + warp;
    if (node >= n) return;
    int beg = g_off[node], end = g_off[node + 1];
    int h = lane >> 3, col = 4 * lane;
    float adv = g_ad1[node * 4 + h];
    float s = 0.f;
    float ax = 0.f, ay = 0.f, az = 0.f, aw = 0.f;

    for (int idx = beg; idx < end; idx += 4) {
        bool n1 = idx + 1 < end, n2 = idx + 2 < end, n3 = idx + 3 < end;
        int s0 = __ldg(&g_csrc[idx]);
        int s1 = n1 ? __ldg(&g_csrc[idx + 1]) : s0;
        int s2 = n2 ? __ldg(&g_csrc[idx + 2]) : s0;
        int s3 = n3 ? __ldg(&g_csrc[idx + 3]) : s0;
        float a0 = __ldg(&g_as1[s0 * 4 + h]);
        float a1 = __ldg(&g_as1[s1 * 4 + h]);
        float a2 = __ldg(&g_as1[s2 * 4 + h]);
        float a3 = __ldg(&g_as1[s3 * 4 + h]);
        uint2 u0 = *(const uint2*)&g_h1b[(size_t)s0 * 128 + col];
        uint2 u1 = *(const uint2*)&g_h1b[(size_t)s1 * 128 + col];
        uint2 u2 = *(const uint2*)&g_h1b[(size_t)s2 * 128 + col];
        uint2 u3 = *(const uint2*)&g_h1b[(size_t)s3 * 128 + col];
        float e0 = __expf(leaky02(a0 + adv));
        float e1 = n1 ? __expf(leaky02(a1 + adv)) : 0.f;
        float e2 = n2 ? __expf(leaky02(a2 + adv)) : 0.f;
        float e3 = n3 ? __expf(leaky02(a3 + adv)) : 0.f;
        s += (e0 + e1) + (e2 + e3);
        float2 p;
        p = bf2f(u0.x); ax = fmaf(e0, p.x, ax); ay = fmaf(e0, p.y, ay);
        p = bf2f(u0.y); az = fmaf(e0, p.x, az); aw = fmaf(e0, p.y, aw);
        p = bf2f(u1.x); ax = fmaf(e1, p.x, ax); ay = fmaf(e1, p.y, ay);
        p = bf2f(u1.y); az = fmaf(e1, p.x, az); aw = fmaf(e1, p.y, aw);
        p = bf2f(u2.x); ax = fmaf(e2, p.x, ax); ay = fmaf(e2, p.y, ay);
        p = bf2f(u2.y); az = fmaf(e2, p.x, az); aw = fmaf(e2, p.y, aw);
        p = bf2f(u3.x); ax = fmaf(e3, p.x, ax); ay = fmaf(e3, p.y, ay);
        p = bf2f(u3.y); az = fmaf(e3, p.x, az); aw = fmaf(e3, p.y, aw);
    }
    float inv = 1.f / (s + 1e-16f);
    float4 bb = *(const float4*)&b1[col];
    float o0 = ax * inv + bb.x;
    float o1 = ay * inv + bb.y;
    float o2 = az * inv + bb.z;
    float o3 = aw * inv + bb.w;
    o0 = o0 > 0.f ? o0 : expm1f(o0);
    o1 = o1 > 0.f ? o1 : expm1f(o1);
    o2 = o2 > 0.f ? o2 : expm1f(o2);
    o3 = o3 > 0.f ? o3 : expm1f(o3);
    *(float4*)&g_y1[(size_t)node * 128 + col] = make_float4(o0, o1, o2, o3);
}

// ---------------- layer-2 aggregation + head-mean + log_softmax ------------
__global__ void __launch_bounds__(256) k_aggr2(const float* __restrict__ b2,
                                               float* __restrict__ out, int n) {
    int warp = threadIdx.x >> 5, lane = threadIdx.x & 31;
    int node = blockIdx.x * 8 + warp;
    if (node >= n) return;
    int beg = g_off[node], end = g_off[node + 1];
    int h = lane >> 3, col = 2 * lane;
    float adv = g_ad2[node * 4 + h];
    float s = 0.f, ax = 0.f, ay = 0.f;

    for (int idx = beg; idx < end; idx += 4) {
        bool n1 = idx + 1 < end, n2 = idx + 2 < end, n3 = idx + 3 < end;
        int s0 = __ldg(&g_csrc[idx]);
        int s1 = n1 ? __ldg(&g_csrc[idx + 1]) : s0;
        int s2 = n2 ? __ldg(&g_csrc[idx + 2]) : s0;
        int s3 = n3 ? __ldg(&g_csrc[idx + 3]) : s0;
        float a0 = __ldg(&g_as2[s0 * 4 + h]);
        float a1 = __ldg(&g_as2[s1 * 4 + h]);
        float a2 = __ldg(&g_as2[s2 * 4 + h]);
        float a3 = __ldg(&g_as2[s3 * 4 + h]);
        uint32_t u0 = *(const uint32_t*)&g_h2b[(size_t)s0 * 64 + col];
        uint32_t u1 = *(const uint32_t*)&g_h2b[(size_t)s1 * 64 + col];
        uint32_t u2 = *(const uint32_t*)&g_h2b[(size_t)s2 * 64 + col];
        uint32_t u3 = *(const uint32_t*)&g_h2b[(size_t)s3 * 64 + col];
        float e0 = __expf(leaky02(a0 + adv));
        float e1 = n1 ? __expf(leaky02(a1 + adv)) : 0.f;
        float e2 = n2 ? __expf(leaky02(a2 + adv)) : 0.f;
        float e3 = n3 ? __expf(leaky02(a3 + adv)) : 0.f;
        s += (e0 + e1) + (e2 + e3);
        float2 p;
        p = bf2f(u0); ax = fmaf(e0, p.x, ax); ay = fmaf(e0, p.y, ay);
        p = bf2f(u1); ax = fmaf(e1, p.x, ax); ay = fmaf(e1, p.y, ay);
        p = bf2f(u2); ax = fmaf(e2, p.x, ax); ay = fmaf(e2, p.y, ay);
        p = bf2f(u3); ax = fmaf(e3, p.x, ax); ay = fmaf(e3, p.y, ay);
    }
    float inv = 1.f / (s + 1e-16f);
    float ox = ax * inv, oy = ay * inv;
    ox += __shfl_xor_sync(0xffffffffu, ox, 8);
    oy += __shfl_xor_sync(0xffffffffu, oy, 8);
    ox += __shfl_xor_sync(0xffffffffu, ox, 16);
    oy += __shfl_xor_sync(0xffffffffu, oy, 16);
    int c0 = 2 * (lane & 7);
    ox = ox * 0.25f + b2[c0];
    oy = oy * 0.25f + b2[c0 + 1];
    float mx = fmaxf(ox, oy);
#pragma unroll
    for (int o = 4; o; o >>= 1) mx = fmaxf(mx, __shfl_xor_sync(0xffffffffu, mx, o));
    float se = __expf(ox - mx) + __expf(oy - mx);
#pragma unroll
    for (int o = 4; o; o >>= 1) se += __shfl_xor_sync(0xffffffffu, se, o);
    float lse = mx + logf(se);
    if (lane < 8)
        *(float2*)&out[(size_t)node * 16 + c0] = make_float2(ox - lse, oy - lse);
}

// ---------------- launcher: R10 schedule (prep, fork CSR || GEMM1) ---------
extern "C" void kernel_launch(void* const* d_in, const int* in_sizes, int n_in,
                              void* d_out, int out_size) {
    const float* x = (const float*)d_in[0];
    const int* ei = (const int*)d_in[1];
    const float* Wemb = (const float*)d_in[2];
    const float* bemb = (const float*)d_in[3];
    const float* W1 = (const float*)d_in[4];
    const float* a_src1 = (const float*)d_in[5];
    const float* a_dst1 = (const float*)d_in[6];
    const float* b1 = (const float*)d_in[7];
    const float* W2 = (const float*)d_in[8];
    const float* a_src2 = (const float*)d_in[9];
    const float* a_dst2 = (const float*)d_in[10];
    const float* b2 = (const float*)d_in[11];
    float* out = (float*)d_out;

    int n = in_sizes[0] / 128;
    int e = in_sizes[1] / 2;
    if (n <= 0 || n > NMAX || e <= 0 || e > EMAX) return;
    const int* src = ei;
    const int* dst = ei + e;
    int nb = (n + 1023) / 1024;
    int nbg = (n + 127) / 128;

    // one-time side-stream + fork/join events (created on first, non-captured call)
    static cudaStream_t sB = nullptr;
    static cudaEvent_t evF = nullptr, evJ = nullptr;
    if (sB == nullptr) {
        cudaStreamCreateWithFlags(&sB, cudaStreamNonBlocking);
        cudaEventCreateWithFlags(&evF, cudaEventDisableTiming);
        cudaEventCreateWithFlags(&evJ, cudaEventDisableTiming);
    }

    int smem1 = 64 * SWW * 4;  // 36864 (half-B for NOUT=128)
    int smem2 = 32 * SWW * 4;  // 18432 (half-B for NOUT=64)
    cudaFuncSetAttribute(k_gemm_mma<128, true>,
                         cudaFuncAttributeMaxDynamicSharedMemorySize, smem1);
    cudaFuncSetAttribute(k_gemm_mma<64, false>,
                         cudaFuncAttributeMaxDynamicSharedMemorySize, smem2);

    int prep_items = 128 * 128 + 64 * 128 + 128 + 64 + n;

    // main stream: prep, then fork
    k_prep<<<(prep_items + 255) / 256, 256>>>(Wemb, bemb, W1, W2, n);
    cudaEventRecord(evF, 0);

    // branch B (side stream): CSR build
    cudaStreamWaitEvent(sB, evF, 0);
    k_hist<<<(e + 255) / 256, 256, 0, sB>>>(dst, e);
    k_scan<<<nb, 1024, 0, sB>>>(n);
    k_scatter<<<(e + 255) / 256, 256, 0, sB>>>(src, dst, e);
    cudaEventRecord(evJ, sB);

    // branch A (main stream): persistent GEMM1 overlaps the CSR build
    k_gemm_mma<128, true><<<2 * PGRP, 256, smem1>>>(x, a_src1, a_dst1, n, nbg);

    // join, then the dependent tail
    cudaStreamWaitEvent(0, evJ, 0);
    k_aggr1<<<(n + 7) / 8, 256>>>(b1, n);
    k_gemm_mma<64, false><<<2 * PGRP, 256, smem2>>>(nullptr, a_src2, a_dst2, n, nbg);
    k_aggr2<<<(n + 7) / 8, 256>>>(b2, out, n);
}